// round 7
// baseline (speedup 1.0000x reference)
#include <cuda_runtime.h>
#include <cstdint>

#define BB 4
#define SS 4096
#define DM 1024
#define DK 64

// Scratch (device globals per allocation-guard rules): 4 MB each
__device__ float g_qh[BB * SS * DK];
__device__ float g_kh[BB * SS * DK];
__device__ float g_vh[BB * SS * DK];
__device__ float g_att[BB * SS * DK];

// ---------------------------------------------------------------------------
// helpers
// ---------------------------------------------------------------------------
__device__ __forceinline__ uint32_t f2tf(float f) {
    uint32_t u;
    asm("cvt.rna.tf32.f32 %0, %1;" : "=r"(u) : "f"(f));
    return u;
}
__device__ __forceinline__ uint32_t tfbits(uint32_t u) {
    uint32_t r;
    asm("cvt.rna.tf32.f32 %0, %1;" : "=r"(r) : "f"(__uint_as_float(u)));
    return r;
}
__device__ __forceinline__ void cvt4_inplace(uint32_t* p) {
    uint4 v = *reinterpret_cast<uint4*>(p);
    v.x = tfbits(v.x); v.y = tfbits(v.y);
    v.z = tfbits(v.z); v.w = tfbits(v.w);
    *reinterpret_cast<uint4*>(p) = v;
}

__device__ __forceinline__ void mma_tf32(float* d, const uint32_t* a,
                                         uint32_t b0, uint32_t b1) {
    asm volatile(
        "mma.sync.aligned.m16n8k8.row.col.f32.tf32.tf32.f32 "
        "{%0,%1,%2,%3}, {%4,%5,%6,%7}, {%8,%9}, {%0,%1,%2,%3};\n"
        : "+f"(d[0]), "+f"(d[1]), "+f"(d[2]), "+f"(d[3])
        : "r"(a[0]), "r"(a[1]), "r"(a[2]), "r"(a[3]), "r"(b0), "r"(b1));
}

__device__ __forceinline__ void cp16(void* s, const void* g) {
    uint32_t sa = (uint32_t)__cvta_generic_to_shared(s);
    asm volatile("cp.async.cg.shared.global [%0], [%1], 16;" :: "r"(sa), "l"(g));
}
__device__ __forceinline__ void cp_commit() {
    asm volatile("cp.async.commit_group;");
}
__device__ __forceinline__ void cp_wait0() {
    asm volatile("cp.async.wait_group 0;");
}

// ---------------------------------------------------------------------------
// QKV projection via tf32 mma + cp.async double buffering + in-place cvt.
// out[m,n] = sum_d X[m,d] * W[n,d] + bias[n].  M=16384, N=64, K=1024.
// Block: 64 rows, 128 threads (4 warps), K-chunks of 64.
// ---------------------------------------------------------------------------
#define XSTR 68
#define WSTR 80
#define PROJ_BUF (64 * XSTR + 64 * WSTR)      // uint32 per buffer
#define PROJ_SMEM (2 * PROJ_BUF * 4)          // bytes

__global__ __launch_bounds__(128) void proj_mma_kernel(const float* __restrict__ X,
                                                       const float* __restrict__ W,
                                                       const float* __restrict__ bias,
                                                       int which)
{
    extern __shared__ uint32_t sp[];

    float* out = (which == 0) ? g_qh : (which == 1) ? g_kh : g_vh;

    const int m0   = blockIdx.x * 64;
    const int t    = threadIdx.x;
    const int w    = t >> 5;
    const int lane = t & 31;
    const int gi   = lane >> 2;
    const int gc   = lane & 3;

    const int srow = t >> 4;            // 0..7 staging row base
    const int sc4  = (t & 15) << 2;     // staging col (floats)

    // prefetch chunk 0 into buffer 0
    {
        uint32_t* Xs = sp;
        uint32_t* Ws = sp + 64 * XSTR;
        #pragma unroll
        for (int j = 0; j < 8; j++) {
            int row = srow + j * 8;
            cp16(&Xs[row * XSTR + sc4], &X[(size_t)(m0 + row) * DM + sc4]);
            cp16(&Ws[row * WSTR + sc4], &W[(size_t)row * DM + sc4]);
        }
        cp_commit();
    }

    float acc[8][4] = {};
    const int ra = 16 * w + gi, rb = ra + 8;

    for (int kc0 = 0; kc0 < 16; kc0++) {
        uint32_t* Xs = sp + (kc0 & 1) * PROJ_BUF;
        uint32_t* Ws = Xs + 64 * XSTR;

        cp_wait0();
        // convert in place: each thread converts exactly the words it staged
        #pragma unroll
        for (int j = 0; j < 8; j++) {
            int row = srow + j * 8;
            cvt4_inplace(&Xs[row * XSTR + sc4]);
            cvt4_inplace(&Ws[row * WSTR + sc4]);
        }
        __syncthreads();

        // prefetch next chunk into the other buffer
        if (kc0 + 1 < 16) {
            uint32_t* Xn = sp + ((kc0 + 1) & 1) * PROJ_BUF;
            uint32_t* Wn = Xn + 64 * XSTR;
            int k0n = (kc0 + 1) * 64;
            #pragma unroll
            for (int j = 0; j < 8; j++) {
                int row = srow + j * 8;
                cp16(&Xn[row * XSTR + sc4], &X[(size_t)(m0 + row) * DM + k0n + sc4]);
                cp16(&Wn[row * WSTR + sc4], &W[(size_t)row * DM + k0n + sc4]);
            }
        }
        cp_commit();

        // A fragments for this k-chunk
        uint32_t aq[8][4];
        #pragma unroll
        for (int kc = 0; kc < 4; kc++) {
            int d = 16 * kc + 4 * gc;
            aq[2*kc  ][0] = Xs[ra * XSTR + d    ];
            aq[2*kc  ][1] = Xs[rb * XSTR + d    ];
            aq[2*kc  ][2] = Xs[ra * XSTR + d + 1];
            aq[2*kc  ][3] = Xs[rb * XSTR + d + 1];
            aq[2*kc+1][0] = Xs[ra * XSTR + d + 2];
            aq[2*kc+1][1] = Xs[rb * XSTR + d + 2];
            aq[2*kc+1][2] = Xs[ra * XSTR + d + 3];
            aq[2*kc+1][3] = Xs[rb * XSTR + d + 3];
        }

        #pragma unroll
        for (int nt = 0; nt < 8; nt++) {
            const uint32_t* kp = Ws + (8 * nt + gi) * WSTR + 4 * gc;
            #pragma unroll
            for (int kc = 0; kc < 4; kc++) {
                uint4 bb = *reinterpret_cast<const uint4*>(kp + 16 * kc);
                mma_tf32(acc[nt], aq[2*kc    ], bb.x, bb.y);
                mma_tf32(acc[nt], aq[2*kc + 1], bb.z, bb.w);
            }
        }
    }

    #pragma unroll
    for (int nt = 0; nt < 8; nt++) {
        int n = 8 * nt + 2 * gc;
        float2 b2 = *(const float2*)&bias[n];
        float2 oa = { acc[nt][0] + b2.x, acc[nt][1] + b2.y };
        *(float2*)&out[(size_t)(m0 + ra) * DK + n] = oa;
        float2 ob = { acc[nt][2] + b2.x, acc[nt][3] + b2.y };
        *(float2*)&out[(size_t)(m0 + rb) * DK + n] = ob;
    }
}

// ---------------------------------------------------------------------------
// Output projection via tf32 mma (single K-chunk; cvt at staging).
// ---------------------------------------------------------------------------
__global__ __launch_bounds__(128) void outproj_mma_kernel(const float* __restrict__ Wo,
                                                          const float* __restrict__ bo,
                                                          float* __restrict__ out)
{
    __shared__ uint32_t As[64 * XSTR];
    __shared__ uint32_t Ws[64 * WSTR];

    const int m0   = blockIdx.x * 64;
    const int n0   = blockIdx.y * 64;
    const int t    = threadIdx.x;
    const int w    = t >> 5;
    const int lane = t & 31;
    const int gi   = lane >> 2;
    const int gc   = lane & 3;

    #pragma unroll
    for (int j = 0; j < 8; j++) {
        int f   = t + j * 128;
        int row = f >> 4;
        int c4  = (f & 15) << 2;
        float4 av = *(const float4*)&g_att[(size_t)(m0 + row) * DK + c4];
        uint4  au = { f2tf(av.x), f2tf(av.y), f2tf(av.z), f2tf(av.w) };
        *reinterpret_cast<uint4*>(&As[row * XSTR + c4]) = au;
        float4 wv = *(const float4*)&Wo[(size_t)(n0 + row) * DK + c4];
        uint4  wu = { f2tf(wv.x), f2tf(wv.y), f2tf(wv.z), f2tf(wv.w) };
        *reinterpret_cast<uint4*>(&Ws[row * WSTR + c4]) = wu;
    }
    __syncthreads();

    const int ra = 16 * w + gi, rb = ra + 8;

    uint32_t aq[8][4];
    #pragma unroll
    for (int kc = 0; kc < 4; kc++) {
        int d = 16 * kc + 4 * gc;
        aq[2*kc  ][0] = As[ra * XSTR + d    ];
        aq[2*kc  ][1] = As[rb * XSTR + d    ];
        aq[2*kc  ][2] = As[ra * XSTR + d + 1];
        aq[2*kc  ][3] = As[rb * XSTR + d + 1];
        aq[2*kc+1][0] = As[ra * XSTR + d + 2];
        aq[2*kc+1][1] = As[rb * XSTR + d + 2];
        aq[2*kc+1][2] = As[ra * XSTR + d + 3];
        aq[2*kc+1][3] = As[rb * XSTR + d + 3];
    }

    float acc[8][4] = {};
    #pragma unroll
    for (int nt = 0; nt < 8; nt++) {
        const uint32_t* kp = Ws + (8 * nt + gi) * WSTR + 4 * gc;
        #pragma unroll
        for (int kc = 0; kc < 4; kc++) {
            uint4 bb = *reinterpret_cast<const uint4*>(kp + 16 * kc);
            mma_tf32(acc[nt], aq[2*kc    ], bb.x, bb.y);
            mma_tf32(acc[nt], aq[2*kc + 1], bb.z, bb.w);
        }
    }

    #pragma unroll
    for (int nt = 0; nt < 8; nt++) {
        int n = n0 + 8 * nt + 2 * gc;
        float2 b2 = *(const float2*)&bo[n];
        float2 oa = { acc[nt][0] + b2.x, acc[nt][1] + b2.y };
        *(float2*)&out[(size_t)(m0 + ra) * DM + n] = oa;
        float2 ob = { acc[nt][2] + b2.x, acc[nt][3] + b2.y };
        *(float2*)&out[(size_t)(m0 + rb) * DM + n] = ob;
    }
}

// ---------------------------------------------------------------------------
// Flash attention, tf32 mma + cp.async double-buffered K/V + in-place cvt.
// Block: 64 queries, 4 warps (16 rows/warp), key tiles of 64, grid 256.
// ---------------------------------------------------------------------------
#define KSTR 80
#define VSTR 84
#define ATTN_BUF (64 * KSTR + 64 * VSTR)      // floats per buffer
#define ATTN_SMEM (2 * ATTN_BUF * 4)          // bytes = 83968

__global__ __launch_bounds__(128) void attn_mma_kernel(const int* __restrict__ mask)
{
    extern __shared__ float sbuf[];

    const int b    = blockIdx.y;
    const int q0   = blockIdx.x * 64;
    const int t    = threadIdx.x;
    const int w    = t >> 5;          // 0..3
    const int lane = t & 31;
    const int gi   = lane >> 2;
    const int gc   = lane & 3;
    const float scale = 0.125f;       // 1/sqrt(64)

    const int skey = t >> 4;          // staging key base (0..7)
    const int sc4  = (t & 15) << 2;   // staging col (floats)

    const float* khb = g_kh + (size_t)b * SS * DK;
    const float* vhb = g_vh + (size_t)b * SS * DK;

    // ---- stage Q through buffer-1 region, extract resident A-fragments ----
    float* Qs = sbuf + ATTN_BUF;      // overlay on buffer 1
    const float* qh = g_qh + ((size_t)b * SS + q0) * DK;
    #pragma unroll
    for (int j = 0; j < 8; j++) {
        int f   = t + j * 128;        // 0..1023
        int row = f >> 4;
        int c4  = (f & 15) << 2;
        *(float4*)&Qs[row * XSTR + c4] = *(const float4*)&qh[row * DK + c4];
    }
    __syncthreads();

    uint32_t aq[8][4];
    {
        int ra = 16 * w + gi, rb = ra + 8;
        #pragma unroll
        for (int kc = 0; kc < 4; kc++) {
            int d = 16 * kc + 4 * gc;
            aq[2*kc  ][0] = f2tf(Qs[ra * XSTR + d    ]);
            aq[2*kc  ][1] = f2tf(Qs[rb * XSTR + d    ]);
            aq[2*kc  ][2] = f2tf(Qs[ra * XSTR + d + 1]);
            aq[2*kc  ][3] = f2tf(Qs[rb * XSTR + d + 1]);
            aq[2*kc+1][0] = f2tf(Qs[ra * XSTR + d + 2]);
            aq[2*kc+1][1] = f2tf(Qs[rb * XSTR + d + 2]);
            aq[2*kc+1][2] = f2tf(Qs[ra * XSTR + d + 3]);
            aq[2*kc+1][3] = f2tf(Qs[rb * XSTR + d + 3]);
        }
    }
    __syncthreads();   // everyone done reading Q before buffer 1 gets reused

    // ---- prefetch key tile 0 into buffer 0 ----
    {
        float* Ks = sbuf;
        float* Vs = sbuf + 64 * KSTR;
        #pragma unroll
        for (int j = 0; j < 8; j++) {
            int key = skey + j * 8;
            cp16(&Ks[key * KSTR + sc4], &khb[(size_t)key * DK + sc4]);
            cp16(&Vs[key * VSTR + sc4], &vhb[(size_t)key * DK + sc4]);
        }
        cp_commit();
    }

    float oacc[8][4] = {};
    float m_a = -1e30f, m_b = -1e30f, l_a = 0.0f, l_b = 0.0f;

    const int qa = q0 + 16 * w + gi;     // row within batch (0..4095)
    const int qb = qa + 8;
    const int2* mrow_a = (const int2*)(mask + (size_t)qa * SS);
    const int2* mrow_b = (const int2*)(mask + (size_t)qb * SS);

    for (int it = 0; it < SS / 64; it++) {
        const int kt = it * 64;
        float* Ks = sbuf + (it & 1) * ATTN_BUF;
        float* Vs = Ks + 64 * KSTR;

        cp_wait0();
        // convert in place: each thread converts exactly the words it staged
        #pragma unroll
        for (int j = 0; j < 8; j++) {
            int key = skey + j * 8;
            cvt4_inplace(reinterpret_cast<uint32_t*>(&Ks[key * KSTR + sc4]));
            cvt4_inplace(reinterpret_cast<uint32_t*>(&Vs[key * VSTR + sc4]));
        }
        __syncthreads();

        // prefetch next tile into the other buffer
        if (it + 1 < SS / 64) {
            float* Kn = sbuf + ((it + 1) & 1) * ATTN_BUF;
            float* Vn = Kn + 64 * KSTR;
            int ktn = kt + 64;
            #pragma unroll
            for (int j = 0; j < 8; j++) {
                int key = skey + j * 8;
                cp16(&Kn[key * KSTR + sc4], &khb[(size_t)(ktn + key) * DK + sc4]);
                cp16(&Vn[key * VSTR + sc4], &vhb[(size_t)(ktn + key) * DK + sc4]);
            }
        }
        cp_commit();

        // ---- GEMM1: S = Q . K^T   (16 rows x 64 keys per warp) ----
        float sacc[8][4];
        #pragma unroll
        for (int nt = 0; nt < 8; nt++) {
            sacc[nt][0] = 0.f; sacc[nt][1] = 0.f;
            sacc[nt][2] = 0.f; sacc[nt][3] = 0.f;
        }
        #pragma unroll
        for (int nt = 0; nt < 8; nt++) {
            const float* kp = Ks + (8 * nt + gi) * KSTR + 4 * gc;
            #pragma unroll
            for (int kc = 0; kc < 4; kc++) {
                uint4 bb = *reinterpret_cast<const uint4*>(kp + 16 * kc);
                mma_tf32(sacc[nt], aq[2*kc    ], bb.x, bb.y);
                mma_tf32(sacc[nt], aq[2*kc + 1], bb.z, bb.w);
            }
        }

        // ---- scale + mask ----
        const int mbase = (kt >> 1) + gc;
        #pragma unroll
        for (int nt = 0; nt < 8; nt++) {
            int2 ma = mrow_a[mbase + 4 * nt];
            int2 mb = mrow_b[mbase + 4 * nt];
            sacc[nt][0] = ma.x ? sacc[nt][0] * scale : -1e9f;
            sacc[nt][1] = ma.y ? sacc[nt][1] * scale : -1e9f;
            sacc[nt][2] = mb.x ? sacc[nt][2] * scale : -1e9f;
            sacc[nt][3] = mb.y ? sacc[nt][3] * scale : -1e9f;
        }

        // ---- online softmax ----
        float mxa = -1e30f, mxb = -1e30f;
        #pragma unroll
        for (int nt = 0; nt < 8; nt++) {
            mxa = fmaxf(mxa, fmaxf(sacc[nt][0], sacc[nt][1]));
            mxb = fmaxf(mxb, fmaxf(sacc[nt][2], sacc[nt][3]));
        }
        mxa = fmaxf(mxa, __shfl_xor_sync(0xffffffffu, mxa, 1));
        mxa = fmaxf(mxa, __shfl_xor_sync(0xffffffffu, mxa, 2));
        mxb = fmaxf(mxb, __shfl_xor_sync(0xffffffffu, mxb, 1));
        mxb = fmaxf(mxb, __shfl_xor_sync(0xffffffffu, mxb, 2));

        float mna = fmaxf(m_a, mxa);
        float mnb = fmaxf(m_b, mxb);
        float ca = __expf(m_a - mna);  m_a = mna;
        float cb = __expf(m_b - mnb);  m_b = mnb;

        uint32_t pf[8][4];
        float sla = 0.0f, slb = 0.0f;
        #pragma unroll
        for (int nt = 0; nt < 8; nt++) {
            float p0 = __expf(sacc[nt][0] - m_a);
            float p1 = __expf(sacc[nt][1] - m_a);
            float p2 = __expf(sacc[nt][2] - m_b);
            float p3 = __expf(sacc[nt][3] - m_b);
            sla += p0 + p1;
            slb += p2 + p3;
            // A-fragment ordering for GEMM2: (c0, c2, c1, c3)
            pf[nt][0] = f2tf(p0);
            pf[nt][1] = f2tf(p2);
            pf[nt][2] = f2tf(p1);
            pf[nt][3] = f2tf(p3);
        }
        sla += __shfl_xor_sync(0xffffffffu, sla, 1);
        sla += __shfl_xor_sync(0xffffffffu, sla, 2);
        slb += __shfl_xor_sync(0xffffffffu, slb, 1);
        slb += __shfl_xor_sync(0xffffffffu, slb, 2);
        l_a = l_a * ca + sla;
        l_b = l_b * cb + slb;

        #pragma unroll
        for (int nt = 0; nt < 8; nt++) {
            oacc[nt][0] *= ca; oacc[nt][1] *= ca;
            oacc[nt][2] *= cb; oacc[nt][3] *= cb;
        }

        // ---- GEMM2: O += P . V ----
        #pragma unroll
        for (int nt = 0; nt < 8; nt++) {
            const float* vp = Vs + 8 * nt + gi;     // dv column base
            #pragma unroll
            for (int g = 0; g < 8; g++) {
                uint32_t b0 = *reinterpret_cast<const uint32_t*>(
                                  vp + (8 * g + 2 * gc)     * VSTR);
                uint32_t b1 = *reinterpret_cast<const uint32_t*>(
                                  vp + (8 * g + 2 * gc + 1) * VSTR);
                mma_tf32(oacc[nt], pf[g], b0, b1);
            }
        }
    }

    // ---- normalize + write ----
    float ia = 1.0f / l_a, ib = 1.0f / l_b;
    float* op = g_att + (size_t)b * SS * DK;
    #pragma unroll
    for (int nt = 0; nt < 8; nt++) {
        float2 oa = { oacc[nt][0] * ia, oacc[nt][1] * ia };
        *(float2*)&op[(size_t)qa * DK + 8 * nt + 2 * gc] = oa;
        float2 ob = { oacc[nt][2] * ib, oacc[nt][3] * ib };
        *(float2*)&op[(size_t)qb * DK + 8 * nt + 2 * gc] = ob;
    }
}

// ---------------------------------------------------------------------------
extern "C" void kernel_launch(void* const* d_in, const int* in_sizes, int n_in,
                              void* d_out, int out_size)
{
    const float* q    = (const float*)d_in[0];
    const float* k    = (const float*)d_in[1];
    const float* v    = (const float*)d_in[2];
    const int*   mask = (const int*)  d_in[3];
    const float* Wq   = (const float*)d_in[4];
    const float* bq   = (const float*)d_in[5];
    const float* Wk   = (const float*)d_in[6];
    const float* bk   = (const float*)d_in[7];
    const float* Wv   = (const float*)d_in[8];
    const float* bv   = (const float*)d_in[9];
    const float* Wo   = (const float*)d_in[10];
    const float* bo   = (const float*)d_in[11];
    float* out = (float*)d_out;

    cudaFuncSetAttribute(proj_mma_kernel,
                         cudaFuncAttributeMaxDynamicSharedMemorySize, PROJ_SMEM);
    cudaFuncSetAttribute(attn_mma_kernel,
                         cudaFuncAttributeMaxDynamicSharedMemorySize, ATTN_SMEM);

    const int M = BB * SS;  // 16384

    proj_mma_kernel<<<M / 64, 128, PROJ_SMEM>>>(q, Wq, bq, 0);
    proj_mma_kernel<<<M / 64, 128, PROJ_SMEM>>>(k, Wk, bk, 1);
    proj_mma_kernel<<<M / 64, 128, PROJ_SMEM>>>(v, Wv, bv, 2);

    attn_mma_kernel<<<dim3(SS / 64, BB), 128, ATTN_SMEM>>>(mask);

    outproj_mma_kernel<<<dim3(M / 64, DM / 64), 128>>>(Wo, bo, out);
}

// round 8
// speedup vs baseline: 1.1806x; 1.1806x over previous
#include <cuda_runtime.h>
#include <cstdint>

#define BB 4
#define SS 4096
#define DM 1024
#define DK 64

// Scratch (device globals per allocation-guard rules): 4 MB each
__device__ float g_qh[BB * SS * DK];
__device__ float g_kh[BB * SS * DK];
__device__ float g_vh[BB * SS * DK];
__device__ float g_att[BB * SS * DK];

// ---------------------------------------------------------------------------
// tf32 helpers
// ---------------------------------------------------------------------------
__device__ __forceinline__ uint32_t f2tf(float f) {
    uint32_t u;
    asm("cvt.rna.tf32.f32 %0, %1;" : "=r"(u) : "f"(f));
    return u;
}

__device__ __forceinline__ void mma_tf32(float* d, const uint32_t* a,
                                         uint32_t b0, uint32_t b1) {
    asm volatile(
        "mma.sync.aligned.m16n8k8.row.col.f32.tf32.tf32.f32 "
        "{%0,%1,%2,%3}, {%4,%5,%6,%7}, {%8,%9}, {%0,%1,%2,%3};\n"
        : "+f"(d[0]), "+f"(d[1]), "+f"(d[2]), "+f"(d[3])
        : "r"(a[0]), "r"(a[1]), "r"(a[2]), "r"(a[3]), "r"(b0), "r"(b1));
}

// ---------------------------------------------------------------------------
// QKV projection via tf32 mma (merged: blockIdx.y selects q/k/v).
// out[m,n] = sum_d X[m,d] * W[n,d] + bias[n].  M=16384, N=64, K=1024.
// Block: 64 rows, 128 threads (4 warps), K-chunks of 64.
// ---------------------------------------------------------------------------
__global__ __launch_bounds__(128, 4) void qkv_mma_kernel(
    const float* __restrict__ q, const float* __restrict__ k,
    const float* __restrict__ v,
    const float* __restrict__ Wq, const float* __restrict__ bq,
    const float* __restrict__ Wk, const float* __restrict__ bk,
    const float* __restrict__ Wv, const float* __restrict__ bv)
{
    __shared__ uint32_t Xs[64 * 68];
    __shared__ uint32_t Ws[64 * 80];

    const int which = blockIdx.y;
    const float* X    = (which == 0) ? q  : (which == 1) ? k  : v;
    const float* W    = (which == 0) ? Wq : (which == 1) ? Wk : Wv;
    const float* bias = (which == 0) ? bq : (which == 1) ? bk : bv;
    float* out        = (which == 0) ? g_qh : (which == 1) ? g_kh : g_vh;

    const int m0   = blockIdx.x * 64;
    const int t    = threadIdx.x;
    const int w    = t >> 5;
    const int lane = t & 31;
    const int gi   = lane >> 2;
    const int gc   = lane & 3;

    float acc[8][4] = {};
    const int ra = 16 * w + gi, rb = ra + 8;

    for (int k0 = 0; k0 < DM; k0 += 64) {
        // stage X tile (64x64) and W tile (64x64), cvt to tf32 at store
        #pragma unroll
        for (int j = 0; j < 8; j++) {
            int f   = t + j * 128;        // 0..1023
            int row = f >> 4;
            int c4  = (f & 15) << 2;
            float4 xv = *(const float4*)&X[(size_t)(m0 + row) * DM + k0 + c4];
            uint4  xu = { f2tf(xv.x), f2tf(xv.y), f2tf(xv.z), f2tf(xv.w) };
            *reinterpret_cast<uint4*>(&Xs[row * 68 + c4]) = xu;
            float4 wv = *(const float4*)&W[(size_t)row * DM + k0 + c4];
            uint4  wu = { f2tf(wv.x), f2tf(wv.y), f2tf(wv.z), f2tf(wv.w) };
            *reinterpret_cast<uint4*>(&Ws[row * 80 + c4]) = wu;
        }
        __syncthreads();

        // A fragments for this k-chunk
        uint32_t aq[8][4];
        #pragma unroll
        for (int kc = 0; kc < 4; kc++) {
            int d = 16 * kc + 4 * gc;
            aq[2*kc  ][0] = Xs[ra * 68 + d    ];
            aq[2*kc  ][1] = Xs[rb * 68 + d    ];
            aq[2*kc  ][2] = Xs[ra * 68 + d + 1];
            aq[2*kc  ][3] = Xs[rb * 68 + d + 1];
            aq[2*kc+1][0] = Xs[ra * 68 + d + 2];
            aq[2*kc+1][1] = Xs[rb * 68 + d + 2];
            aq[2*kc+1][2] = Xs[ra * 68 + d + 3];
            aq[2*kc+1][3] = Xs[rb * 68 + d + 3];
        }

        #pragma unroll
        for (int nt = 0; nt < 8; nt++) {
            const uint32_t* kp = Ws + (8 * nt + gi) * 80 + 4 * gc;
            #pragma unroll
            for (int kc = 0; kc < 4; kc++) {
                uint4 bb = *reinterpret_cast<const uint4*>(kp + 16 * kc);
                mma_tf32(acc[nt], aq[2*kc    ], bb.x, bb.y);
                mma_tf32(acc[nt], aq[2*kc + 1], bb.z, bb.w);
            }
        }
        __syncthreads();
    }

    #pragma unroll
    for (int nt = 0; nt < 8; nt++) {
        int n = 8 * nt + 2 * gc;
        float2 b2 = *(const float2*)&bias[n];
        float2 oa = { acc[nt][0] + b2.x, acc[nt][1] + b2.y };
        *(float2*)&out[(size_t)(m0 + ra) * DK + n] = oa;
        float2 ob = { acc[nt][2] + b2.x, acc[nt][3] + b2.y };
        *(float2*)&out[(size_t)(m0 + rb) * DK + n] = ob;
    }
}

// ---------------------------------------------------------------------------
// Output projection via tf32 mma: out[m,n] = sum_v att[m,v]*Wo[n,v] + bo[n]
// M = 16384, N = 1024, K = 64.  Block: 64 rows x 64 cols, 128 threads.
// ---------------------------------------------------------------------------
__global__ __launch_bounds__(128, 4) void outproj_mma_kernel(const float* __restrict__ Wo,
                                                             const float* __restrict__ bo,
                                                             float* __restrict__ out)
{
    __shared__ uint32_t As[64 * 68];
    __shared__ uint32_t Ws[64 * 80];

    const int m0   = blockIdx.x * 64;
    const int n0   = blockIdx.y * 64;
    const int t    = threadIdx.x;
    const int w    = t >> 5;
    const int lane = t & 31;
    const int gi   = lane >> 2;
    const int gc   = lane & 3;

    #pragma unroll
    for (int j = 0; j < 8; j++) {
        int f   = t + j * 128;
        int row = f >> 4;
        int c4  = (f & 15) << 2;
        float4 av = *(const float4*)&g_att[(size_t)(m0 + row) * DK + c4];
        uint4  au = { f2tf(av.x), f2tf(av.y), f2tf(av.z), f2tf(av.w) };
        *reinterpret_cast<uint4*>(&As[row * 68 + c4]) = au;
        float4 wv = *(const float4*)&Wo[(size_t)(n0 + row) * DK + c4];
        uint4  wu = { f2tf(wv.x), f2tf(wv.y), f2tf(wv.z), f2tf(wv.w) };
        *reinterpret_cast<uint4*>(&Ws[row * 80 + c4]) = wu;
    }
    __syncthreads();

    const int ra = 16 * w + gi, rb = ra + 8;

    uint32_t aq[8][4];
    #pragma unroll
    for (int kc = 0; kc < 4; kc++) {
        int d = 16 * kc + 4 * gc;
        aq[2*kc  ][0] = As[ra * 68 + d    ];
        aq[2*kc  ][1] = As[rb * 68 + d    ];
        aq[2*kc  ][2] = As[ra * 68 + d + 1];
        aq[2*kc  ][3] = As[rb * 68 + d + 1];
        aq[2*kc+1][0] = As[ra * 68 + d + 2];
        aq[2*kc+1][1] = As[rb * 68 + d + 2];
        aq[2*kc+1][2] = As[ra * 68 + d + 3];
        aq[2*kc+1][3] = As[rb * 68 + d + 3];
    }

    float acc[8][4] = {};
    #pragma unroll
    for (int nt = 0; nt < 8; nt++) {
        const uint32_t* kp = Ws + (8 * nt + gi) * 80 + 4 * gc;
        #pragma unroll
        for (int kc = 0; kc < 4; kc++) {
            uint4 bb = *reinterpret_cast<const uint4*>(kp + 16 * kc);
            mma_tf32(acc[nt], aq[2*kc    ], bb.x, bb.y);
            mma_tf32(acc[nt], aq[2*kc + 1], bb.z, bb.w);
        }
    }

    #pragma unroll
    for (int nt = 0; nt < 8; nt++) {
        int n = n0 + 8 * nt + 2 * gc;
        float2 b2 = *(const float2*)&bo[n];
        float2 oa = { acc[nt][0] + b2.x, acc[nt][1] + b2.y };
        *(float2*)&out[(size_t)(m0 + ra) * DM + n] = oa;
        float2 ob = { acc[nt][2] + b2.x, acc[nt][3] + b2.y };
        *(float2*)&out[(size_t)(m0 + rb) * DM + n] = ob;
    }
}

// ---------------------------------------------------------------------------
// Flash attention with tf32 mma.sync (m16n8k8).  R3 core + register diet:
// P fragments overwrite sacc in place (no pf array), launch_bounds(128,4)
// -> <=128 regs -> 4 blocks/SM (16 warps).
// Block: 64 queries, 4 warps (16 rows/warp), key tiles of 64, grid 256.
// ---------------------------------------------------------------------------
#define KSTR 80
#define VSTR 84

__global__ __launch_bounds__(128, 4) void attn_mma_kernel(const int* __restrict__ mask)
{
    __shared__ float sbuf[64 * KSTR + 64 * VSTR];   // 41984 B
    float* Ks = sbuf;                // [64][KSTR]
    float* Vs = sbuf + 64 * KSTR;    // [64][VSTR]
    float* Qs = sbuf;                // staging overlay [64][68]

    const int b    = blockIdx.y;
    const int q0   = blockIdx.x * 64;
    const int t    = threadIdx.x;
    const int w    = t >> 5;          // 0..3
    const int lane = t & 31;
    const int gi   = lane >> 2;
    const int gc   = lane & 3;
    const float scale = 0.125f;       // 1/sqrt(64)

    // ---- stage Q through smem, extract resident A-fragments ----
    const float* qh = g_qh + ((size_t)b * SS + q0) * DK;
    #pragma unroll
    for (int j = 0; j < 8; j++) {
        int f   = t + j * 128;        // 0..1023
        int row = f >> 4;
        int c4  = (f & 15) << 2;
        *(float4*)&Qs[row * 68 + c4] = *(const float4*)&qh[row * DK + c4];
    }
    __syncthreads();

    uint32_t aq[8][4];
    {
        int ra = 16 * w + gi, rb = ra + 8;
        #pragma unroll
        for (int kc = 0; kc < 4; kc++) {
            int d = 16 * kc + 4 * gc;
            aq[2*kc  ][0] = f2tf(Qs[ra * 68 + d    ]);
            aq[2*kc  ][1] = f2tf(Qs[rb * 68 + d    ]);
            aq[2*kc  ][2] = f2tf(Qs[ra * 68 + d + 1]);
            aq[2*kc  ][3] = f2tf(Qs[rb * 68 + d + 1]);
            aq[2*kc+1][0] = f2tf(Qs[ra * 68 + d + 2]);
            aq[2*kc+1][1] = f2tf(Qs[rb * 68 + d + 2]);
            aq[2*kc+1][2] = f2tf(Qs[ra * 68 + d + 3]);
            aq[2*kc+1][3] = f2tf(Qs[rb * 68 + d + 3]);
        }
    }
    __syncthreads();   // everyone done reading Q before Ks overwrites it

    float oacc[8][4] = {};
    float m_a = -1e30f, m_b = -1e30f, l_a = 0.0f, l_b = 0.0f;

    const int qa = q0 + 16 * w + gi;     // row within batch (0..4095)
    const int qb = qa + 8;

    const float* khb = g_kh + (size_t)b * SS * DK;
    const float* vhb = g_vh + (size_t)b * SS * DK;
    const int2* mrow_a = (const int2*)(mask + (size_t)qa * SS);
    const int2* mrow_b = (const int2*)(mask + (size_t)qb * SS);

    for (int kt = 0; kt < SS; kt += 64) {
        // ---- stage K, V tiles (cvt to tf32 at store) ----
        #pragma unroll
        for (int j = 0; j < 8; j++) {
            int f   = t + j * 128;      // 0..1023
            int key = f >> 4;
            int c4  = (f & 15) << 2;
            float4 kv = *(const float4*)&khb[(size_t)(kt + key) * DK + c4];
            uint4  ku = { f2tf(kv.x), f2tf(kv.y), f2tf(kv.z), f2tf(kv.w) };
            *reinterpret_cast<uint4*>(Ks + key * KSTR + c4) = ku;
            float4 vv = *(const float4*)&vhb[(size_t)(kt + key) * DK + c4];
            uint4  vu = { f2tf(vv.x), f2tf(vv.y), f2tf(vv.z), f2tf(vv.w) };
            *reinterpret_cast<uint4*>(Vs + key * VSTR + c4) = vu;
        }
        __syncthreads();

        // ---- GEMM1: S = Q . K^T   (16 rows x 64 keys per warp) ----
        float sacc[8][4];
        #pragma unroll
        for (int nt = 0; nt < 8; nt++) {
            sacc[nt][0] = 0.f; sacc[nt][1] = 0.f;
            sacc[nt][2] = 0.f; sacc[nt][3] = 0.f;
        }
        #pragma unroll
        for (int nt = 0; nt < 8; nt++) {
            const float* kp = Ks + (8 * nt + gi) * KSTR + 4 * gc;
            #pragma unroll
            for (int kc = 0; kc < 4; kc++) {
                uint4 bb = *reinterpret_cast<const uint4*>(kp + 16 * kc);
                mma_tf32(sacc[nt], aq[2*kc    ], bb.x, bb.y);
                mma_tf32(sacc[nt], aq[2*kc + 1], bb.z, bb.w);
            }
        }

        // ---- scale + mask ----
        const int mbase = (kt >> 1) + gc;
        #pragma unroll
        for (int nt = 0; nt < 8; nt++) {
            int2 ma = mrow_a[mbase + 4 * nt];
            int2 mb = mrow_b[mbase + 4 * nt];
            sacc[nt][0] = ma.x ? sacc[nt][0] * scale : -1e9f;
            sacc[nt][1] = ma.y ? sacc[nt][1] * scale : -1e9f;
            sacc[nt][2] = mb.x ? sacc[nt][2] * scale : -1e9f;
            sacc[nt][3] = mb.y ? sacc[nt][3] * scale : -1e9f;
        }

        // ---- online softmax ----
        float mxa = -1e30f, mxb = -1e30f;
        #pragma unroll
        for (int nt = 0; nt < 8; nt++) {
            mxa = fmaxf(mxa, fmaxf(sacc[nt][0], sacc[nt][1]));
            mxb = fmaxf(mxb, fmaxf(sacc[nt][2], sacc[nt][3]));
        }
        mxa = fmaxf(mxa, __shfl_xor_sync(0xffffffffu, mxa, 1));
        mxa = fmaxf(mxa, __shfl_xor_sync(0xffffffffu, mxa, 2));
        mxb = fmaxf(mxb, __shfl_xor_sync(0xffffffffu, mxb, 1));
        mxb = fmaxf(mxb, __shfl_xor_sync(0xffffffffu, mxb, 2));

        float mna = fmaxf(m_a, mxa);
        float mnb = fmaxf(m_b, mxb);
        float ca = __expf(m_a - mna);  m_a = mna;
        float cb = __expf(m_b - mnb);  m_b = mnb;

        // ---- P = exp(S - m), written back IN PLACE into sacc as tf32 A-frags
        //      with the (c0, c2, c1, c3) permutation for GEMM2 ----
        float sla = 0.0f, slb = 0.0f;
        #pragma unroll
        for (int nt = 0; nt < 8; nt++) {
            float p0 = __expf(sacc[nt][0] - m_a);
            float p1 = __expf(sacc[nt][1] - m_a);
            float p2 = __expf(sacc[nt][2] - m_b);
            float p3 = __expf(sacc[nt][3] - m_b);
            sla += p0 + p1;
            slb += p2 + p3;
            sacc[nt][0] = __uint_as_float(f2tf(p0));
            sacc[nt][1] = __uint_as_float(f2tf(p2));
            sacc[nt][2] = __uint_as_float(f2tf(p1));
            sacc[nt][3] = __uint_as_float(f2tf(p3));
        }
        sla += __shfl_xor_sync(0xffffffffu, sla, 1);
        sla += __shfl_xor_sync(0xffffffffu, sla, 2);
        slb += __shfl_xor_sync(0xffffffffu, slb, 1);
        slb += __shfl_xor_sync(0xffffffffu, slb, 2);
        l_a = l_a * ca + sla;
        l_b = l_b * cb + slb;

        #pragma unroll
        for (int nt = 0; nt < 8; nt++) {
            oacc[nt][0] *= ca; oacc[nt][1] *= ca;
            oacc[nt][2] *= cb; oacc[nt][3] *= cb;
        }

        // ---- GEMM2: O += P . V ----
        #pragma unroll
        for (int nt = 0; nt < 8; nt++) {
            const float* vp = Vs + 8 * nt + gi;     // dv column base
            #pragma unroll
            for (int g = 0; g < 8; g++) {
                uint32_t b0 = *reinterpret_cast<const uint32_t*>(
                                  vp + (8 * g + 2 * gc)     * VSTR);
                uint32_t b1 = *reinterpret_cast<const uint32_t*>(
                                  vp + (8 * g + 2 * gc + 1) * VSTR);
                mma_tf32(oacc[nt], reinterpret_cast<const uint32_t*>(sacc[g]),
                         b0, b1);
            }
        }
        __syncthreads();   // tiles consumed; safe to overwrite next iteration
    }

    // ---- normalize + write ----
    float ia = 1.0f / l_a, ib = 1.0f / l_b;
    float* op = g_att + (size_t)b * SS * DK;
    #pragma unroll
    for (int nt = 0; nt < 8; nt++) {
        float2 oa = { oacc[nt][0] * ia, oacc[nt][1] * ia };
        *(float2*)&op[(size_t)qa * DK + 8 * nt + 2 * gc] = oa;
        float2 ob = { oacc[nt][2] * ib, oacc[nt][3] * ib };
        *(float2*)&op[(size_t)qb * DK + 8 * nt + 2 * gc] = ob;
    }
}

// ---------------------------------------------------------------------------
extern "C" void kernel_launch(void* const* d_in, const int* in_sizes, int n_in,
                              void* d_out, int out_size)
{
    const float* q    = (const float*)d_in[0];
    const float* k    = (const float*)d_in[1];
    const float* v    = (const float*)d_in[2];
    const int*   mask = (const int*)  d_in[3];
    const float* Wq   = (const float*)d_in[4];
    const float* bq   = (const float*)d_in[5];
    const float* Wk   = (const float*)d_in[6];
    const float* bk   = (const float*)d_in[7];
    const float* Wv   = (const float*)d_in[8];
    const float* bv   = (const float*)d_in[9];
    const float* Wo   = (const float*)d_in[10];
    const float* bo   = (const float*)d_in[11];
    float* out = (float*)d_out;

    const int M = BB * SS;  // 16384

    qkv_mma_kernel<<<dim3(M / 64, 3), 128>>>(q, k, v, Wq, bq, Wk, bk, Wv, bv);

    attn_mma_kernel<<<dim3(SS / 64, BB), 128>>>(mask);

    outproj_mma_kernel<<<dim3(M / 64, DM / 64), 128>>>(Wo, bo, out);
}

// round 9
// speedup vs baseline: 1.7201x; 1.4570x over previous
#include <cuda_runtime.h>
#include <cstdint>

#define BB 4
#define SS 4096
#define DM 1024
#define DK 64
#define NSPLIT 4
#define SPLITLEN (SS / NSPLIT)   // 1024 keys per split
#define NR (BB * SS)             // 16384 rows

// Scratch (device globals per allocation-guard rules)
__device__ float g_qh[BB * SS * DK];
__device__ float g_kh[BB * SS * DK];
__device__ float g_vh[BB * SS * DK];
__device__ float g_att[BB * SS * DK];
__device__ float g_op[NSPLIT][BB * SS * DK];   // unnormalized partial O
__device__ float g_m[NSPLIT * NR];             // per-row running max
__device__ float g_l[NSPLIT * NR];             // per-row running sum

// ---------------------------------------------------------------------------
// tf32 helpers
// ---------------------------------------------------------------------------
__device__ __forceinline__ uint32_t f2tf(float f) {
    uint32_t u;
    asm("cvt.rna.tf32.f32 %0, %1;" : "=r"(u) : "f"(f));
    return u;
}

__device__ __forceinline__ void mma_tf32(float* d, const uint32_t* a,
                                         uint32_t b0, uint32_t b1) {
    asm volatile(
        "mma.sync.aligned.m16n8k8.row.col.f32.tf32.tf32.f32 "
        "{%0,%1,%2,%3}, {%4,%5,%6,%7}, {%8,%9}, {%0,%1,%2,%3};\n"
        : "+f"(d[0]), "+f"(d[1]), "+f"(d[2]), "+f"(d[3])
        : "r"(a[0]), "r"(a[1]), "r"(a[2]), "r"(a[3]), "r"(b0), "r"(b1));
}

// ---------------------------------------------------------------------------
// QKV projection via tf32 mma (merged: blockIdx.y selects q/k/v).
// ---------------------------------------------------------------------------
__global__ __launch_bounds__(128, 4) void qkv_mma_kernel(
    const float* __restrict__ q, const float* __restrict__ k,
    const float* __restrict__ v,
    const float* __restrict__ Wq, const float* __restrict__ bq,
    const float* __restrict__ Wk, const float* __restrict__ bk,
    const float* __restrict__ Wv, const float* __restrict__ bv)
{
    __shared__ uint32_t Xs[64 * 68];
    __shared__ uint32_t Ws[64 * 80];

    const int which = blockIdx.y;
    const float* X    = (which == 0) ? q  : (which == 1) ? k  : v;
    const float* W    = (which == 0) ? Wq : (which == 1) ? Wk : Wv;
    const float* bias = (which == 0) ? bq : (which == 1) ? bk : bv;
    float* out        = (which == 0) ? g_qh : (which == 1) ? g_kh : g_vh;

    const int m0   = blockIdx.x * 64;
    const int t    = threadIdx.x;
    const int w    = t >> 5;
    const int lane = t & 31;
    const int gi   = lane >> 2;
    const int gc   = lane & 3;

    float acc[8][4] = {};
    const int ra = 16 * w + gi, rb = ra + 8;

    for (int k0 = 0; k0 < DM; k0 += 64) {
        #pragma unroll
        for (int j = 0; j < 8; j++) {
            int f   = t + j * 128;
            int row = f >> 4;
            int c4  = (f & 15) << 2;
            float4 xv = *(const float4*)&X[(size_t)(m0 + row) * DM + k0 + c4];
            uint4  xu = { f2tf(xv.x), f2tf(xv.y), f2tf(xv.z), f2tf(xv.w) };
            *reinterpret_cast<uint4*>(&Xs[row * 68 + c4]) = xu;
            float4 wv = *(const float4*)&W[(size_t)row * DM + k0 + c4];
            uint4  wu = { f2tf(wv.x), f2tf(wv.y), f2tf(wv.z), f2tf(wv.w) };
            *reinterpret_cast<uint4*>(&Ws[row * 80 + c4]) = wu;
        }
        __syncthreads();

        uint32_t aq[8][4];
        #pragma unroll
        for (int kc = 0; kc < 4; kc++) {
            int d = 16 * kc + 4 * gc;
            aq[2*kc  ][0] = Xs[ra * 68 + d    ];
            aq[2*kc  ][1] = Xs[rb * 68 + d    ];
            aq[2*kc  ][2] = Xs[ra * 68 + d + 1];
            aq[2*kc  ][3] = Xs[rb * 68 + d + 1];
            aq[2*kc+1][0] = Xs[ra * 68 + d + 2];
            aq[2*kc+1][1] = Xs[rb * 68 + d + 2];
            aq[2*kc+1][2] = Xs[ra * 68 + d + 3];
            aq[2*kc+1][3] = Xs[rb * 68 + d + 3];
        }

        #pragma unroll
        for (int nt = 0; nt < 8; nt++) {
            const uint32_t* kp = Ws + (8 * nt + gi) * 80 + 4 * gc;
            #pragma unroll
            for (int kc = 0; kc < 4; kc++) {
                uint4 bb = *reinterpret_cast<const uint4*>(kp + 16 * kc);
                mma_tf32(acc[nt], aq[2*kc    ], bb.x, bb.y);
                mma_tf32(acc[nt], aq[2*kc + 1], bb.z, bb.w);
            }
        }
        __syncthreads();
    }

    #pragma unroll
    for (int nt = 0; nt < 8; nt++) {
        int n = 8 * nt + 2 * gc;
        float2 b2 = *(const float2*)&bias[n];
        float2 oa = { acc[nt][0] + b2.x, acc[nt][1] + b2.y };
        *(float2*)&out[(size_t)(m0 + ra) * DK + n] = oa;
        float2 ob = { acc[nt][2] + b2.x, acc[nt][3] + b2.y };
        *(float2*)&out[(size_t)(m0 + rb) * DK + n] = ob;
    }
}

// ---------------------------------------------------------------------------
// Output projection via tf32 mma.
// ---------------------------------------------------------------------------
__global__ __launch_bounds__(128, 4) void outproj_mma_kernel(const float* __restrict__ Wo,
                                                             const float* __restrict__ bo,
                                                             float* __restrict__ out)
{
    __shared__ uint32_t As[64 * 68];
    __shared__ uint32_t Ws[64 * 80];

    const int m0   = blockIdx.x * 64;
    const int n0   = blockIdx.y * 64;
    const int t    = threadIdx.x;
    const int w    = t >> 5;
    const int lane = t & 31;
    const int gi   = lane >> 2;
    const int gc   = lane & 3;

    #pragma unroll
    for (int j = 0; j < 8; j++) {
        int f   = t + j * 128;
        int row = f >> 4;
        int c4  = (f & 15) << 2;
        float4 av = *(const float4*)&g_att[(size_t)(m0 + row) * DK + c4];
        uint4  au = { f2tf(av.x), f2tf(av.y), f2tf(av.z), f2tf(av.w) };
        *reinterpret_cast<uint4*>(&As[row * 68 + c4]) = au;
        float4 wv = *(const float4*)&Wo[(size_t)(n0 + row) * DK + c4];
        uint4  wu = { f2tf(wv.x), f2tf(wv.y), f2tf(wv.z), f2tf(wv.w) };
        *reinterpret_cast<uint4*>(&Ws[row * 80 + c4]) = wu;
    }
    __syncthreads();

    const int ra = 16 * w + gi, rb = ra + 8;

    uint32_t aq[8][4];
    #pragma unroll
    for (int kc = 0; kc < 4; kc++) {
        int d = 16 * kc + 4 * gc;
        aq[2*kc  ][0] = As[ra * 68 + d    ];
        aq[2*kc  ][1] = As[rb * 68 + d    ];
        aq[2*kc  ][2] = As[ra * 68 + d + 1];
        aq[2*kc  ][3] = As[rb * 68 + d + 1];
        aq[2*kc+1][0] = As[ra * 68 + d + 2];
        aq[2*kc+1][1] = As[rb * 68 + d + 2];
        aq[2*kc+1][2] = As[ra * 68 + d + 3];
        aq[2*kc+1][3] = As[rb * 68 + d + 3];
    }

    float acc[8][4] = {};
    #pragma unroll
    for (int nt = 0; nt < 8; nt++) {
        const uint32_t* kp = Ws + (8 * nt + gi) * 80 + 4 * gc;
        #pragma unroll
        for (int kc = 0; kc < 4; kc++) {
            uint4 bb = *reinterpret_cast<const uint4*>(kp + 16 * kc);
            mma_tf32(acc[nt], aq[2*kc    ], bb.x, bb.y);
            mma_tf32(acc[nt], aq[2*kc + 1], bb.z, bb.w);
        }
    }

    #pragma unroll
    for (int nt = 0; nt < 8; nt++) {
        int n = n0 + 8 * nt + 2 * gc;
        float2 b2 = *(const float2*)&bo[n];
        float2 oa = { acc[nt][0] + b2.x, acc[nt][1] + b2.y };
        *(float2*)&out[(size_t)(m0 + ra) * DM + n] = oa;
        float2 ob = { acc[nt][2] + b2.x, acc[nt][3] + b2.y };
        *(float2*)&out[(size_t)(m0 + rb) * DM + n] = ob;
    }
}

// ---------------------------------------------------------------------------
// Split-K flash attention.  Grid (SS/64, BB, NSPLIT) = 1024 blocks.
// Each block: 64 queries x 1024 keys (16 tiles).  Writes unnormalized O
// partial + per-row (m, l); combine kernel merges the 4 splits.
// ---------------------------------------------------------------------------
#define KSTR 80
#define VSTR 84

__global__ __launch_bounds__(128, 4) void attn_mma_kernel(const int* __restrict__ mask)
{
    __shared__ float sbuf[64 * KSTR + 64 * VSTR];   // 41984 B
    float* Ks = sbuf;                // [64][KSTR]
    float* Vs = sbuf + 64 * KSTR;    // [64][VSTR]
    float* Qs = sbuf;                // staging overlay [64][68]

    const int b     = blockIdx.y;
    const int q0    = blockIdx.x * 64;
    const int split = blockIdx.z;
    const int t     = threadIdx.x;
    const int w     = t >> 5;          // 0..3
    const int lane  = t & 31;
    const int gi    = lane >> 2;
    const int gc    = lane & 3;
    const float scale = 0.125f;        // 1/sqrt(64)

    // ---- stage Q through smem, extract resident A-fragments ----
    const float* qh = g_qh + ((size_t)b * SS + q0) * DK;
    #pragma unroll
    for (int j = 0; j < 8; j++) {
        int f   = t + j * 128;        // 0..1023
        int row = f >> 4;
        int c4  = (f & 15) << 2;
        *(float4*)&Qs[row * 68 + c4] = *(const float4*)&qh[row * DK + c4];
    }
    __syncthreads();

    uint32_t aq[8][4];
    {
        int ra = 16 * w + gi, rb = ra + 8;
        #pragma unroll
        for (int kc = 0; kc < 4; kc++) {
            int d = 16 * kc + 4 * gc;
            aq[2*kc  ][0] = f2tf(Qs[ra * 68 + d    ]);
            aq[2*kc  ][1] = f2tf(Qs[rb * 68 + d    ]);
            aq[2*kc  ][2] = f2tf(Qs[ra * 68 + d + 1]);
            aq[2*kc  ][3] = f2tf(Qs[rb * 68 + d + 1]);
            aq[2*kc+1][0] = f2tf(Qs[ra * 68 + d + 2]);
            aq[2*kc+1][1] = f2tf(Qs[rb * 68 + d + 2]);
            aq[2*kc+1][2] = f2tf(Qs[ra * 68 + d + 3]);
            aq[2*kc+1][3] = f2tf(Qs[rb * 68 + d + 3]);
        }
    }
    __syncthreads();   // everyone done reading Q before Ks overwrites it

    float oacc[8][4] = {};
    float m_a = -1e30f, m_b = -1e30f, l_a = 0.0f, l_b = 0.0f;

    const int qa = q0 + 16 * w + gi;     // row within batch (0..4095)
    const int qb = qa + 8;

    const float* khb = g_kh + (size_t)b * SS * DK;
    const float* vhb = g_vh + (size_t)b * SS * DK;
    const int2* mrow_a = (const int2*)(mask + (size_t)qa * SS);
    const int2* mrow_b = (const int2*)(mask + (size_t)qb * SS);

    const int kbeg = split * SPLITLEN;
    const int kend = kbeg + SPLITLEN;

    for (int kt = kbeg; kt < kend; kt += 64) {
        // ---- stage K, V tiles (cvt to tf32 at store) ----
        #pragma unroll
        for (int j = 0; j < 8; j++) {
            int f   = t + j * 128;      // 0..1023
            int key = f >> 4;
            int c4  = (f & 15) << 2;
            float4 kv = *(const float4*)&khb[(size_t)(kt + key) * DK + c4];
            uint4  ku = { f2tf(kv.x), f2tf(kv.y), f2tf(kv.z), f2tf(kv.w) };
            *reinterpret_cast<uint4*>(Ks + key * KSTR + c4) = ku;
            float4 vv = *(const float4*)&vhb[(size_t)(kt + key) * DK + c4];
            uint4  vu = { f2tf(vv.x), f2tf(vv.y), f2tf(vv.z), f2tf(vv.w) };
            *reinterpret_cast<uint4*>(Vs + key * VSTR + c4) = vu;
        }
        __syncthreads();

        // ---- GEMM1: S = Q . K^T ----
        float sacc[8][4];
        #pragma unroll
        for (int nt = 0; nt < 8; nt++) {
            sacc[nt][0] = 0.f; sacc[nt][1] = 0.f;
            sacc[nt][2] = 0.f; sacc[nt][3] = 0.f;
        }
        #pragma unroll
        for (int nt = 0; nt < 8; nt++) {
            const float* kp = Ks + (8 * nt + gi) * KSTR + 4 * gc;
            #pragma unroll
            for (int kc = 0; kc < 4; kc++) {
                uint4 bb = *reinterpret_cast<const uint4*>(kp + 16 * kc);
                mma_tf32(sacc[nt], aq[2*kc    ], bb.x, bb.y);
                mma_tf32(sacc[nt], aq[2*kc + 1], bb.z, bb.w);
            }
        }

        // ---- scale + mask ----
        const int mbase = (kt >> 1) + gc;
        #pragma unroll
        for (int nt = 0; nt < 8; nt++) {
            int2 ma = mrow_a[mbase + 4 * nt];
            int2 mb = mrow_b[mbase + 4 * nt];
            sacc[nt][0] = ma.x ? sacc[nt][0] * scale : -1e9f;
            sacc[nt][1] = ma.y ? sacc[nt][1] * scale : -1e9f;
            sacc[nt][2] = mb.x ? sacc[nt][2] * scale : -1e9f;
            sacc[nt][3] = mb.y ? sacc[nt][3] * scale : -1e9f;
        }

        // ---- online softmax ----
        float mxa = -1e30f, mxb = -1e30f;
        #pragma unroll
        for (int nt = 0; nt < 8; nt++) {
            mxa = fmaxf(mxa, fmaxf(sacc[nt][0], sacc[nt][1]));
            mxb = fmaxf(mxb, fmaxf(sacc[nt][2], sacc[nt][3]));
        }
        mxa = fmaxf(mxa, __shfl_xor_sync(0xffffffffu, mxa, 1));
        mxa = fmaxf(mxa, __shfl_xor_sync(0xffffffffu, mxa, 2));
        mxb = fmaxf(mxb, __shfl_xor_sync(0xffffffffu, mxb, 1));
        mxb = fmaxf(mxb, __shfl_xor_sync(0xffffffffu, mxb, 2));

        float mna = fmaxf(m_a, mxa);
        float mnb = fmaxf(m_b, mxb);
        float ca = __expf(m_a - mna);  m_a = mna;
        float cb = __expf(m_b - mnb);  m_b = mnb;

        // ---- P = exp(S - m) in place (tf32, permuted (c0,c2,c1,c3)) ----
        float sla = 0.0f, slb = 0.0f;
        #pragma unroll
        for (int nt = 0; nt < 8; nt++) {
            float p0 = __expf(sacc[nt][0] - m_a);
            float p1 = __expf(sacc[nt][1] - m_a);
            float p2 = __expf(sacc[nt][2] - m_b);
            float p3 = __expf(sacc[nt][3] - m_b);
            sla += p0 + p1;
            slb += p2 + p3;
            sacc[nt][0] = __uint_as_float(f2tf(p0));
            sacc[nt][1] = __uint_as_float(f2tf(p2));
            sacc[nt][2] = __uint_as_float(f2tf(p1));
            sacc[nt][3] = __uint_as_float(f2tf(p3));
        }
        sla += __shfl_xor_sync(0xffffffffu, sla, 1);
        sla += __shfl_xor_sync(0xffffffffu, sla, 2);
        slb += __shfl_xor_sync(0xffffffffu, slb, 1);
        slb += __shfl_xor_sync(0xffffffffu, slb, 2);
        l_a = l_a * ca + sla;
        l_b = l_b * cb + slb;

        #pragma unroll
        for (int nt = 0; nt < 8; nt++) {
            oacc[nt][0] *= ca; oacc[nt][1] *= ca;
            oacc[nt][2] *= cb; oacc[nt][3] *= cb;
        }

        // ---- GEMM2: O += P . V ----
        #pragma unroll
        for (int nt = 0; nt < 8; nt++) {
            const float* vp = Vs + 8 * nt + gi;     // dv column base
            #pragma unroll
            for (int g = 0; g < 8; g++) {
                uint32_t b0 = *reinterpret_cast<const uint32_t*>(
                                  vp + (8 * g + 2 * gc)     * VSTR);
                uint32_t b1 = *reinterpret_cast<const uint32_t*>(
                                  vp + (8 * g + 2 * gc + 1) * VSTR);
                mma_tf32(oacc[nt], reinterpret_cast<const uint32_t*>(sacc[g]),
                         b0, b1);
            }
        }
        __syncthreads();   // tiles consumed; safe to overwrite next iteration
    }

    // ---- write unnormalized partial O + (m, l) ----
    const size_t rowa = (size_t)b * SS + qa;
    const size_t rowb = (size_t)b * SS + qb;
    float* op = g_op[split];
    #pragma unroll
    for (int nt = 0; nt < 8; nt++) {
        float2 oa = { oacc[nt][0], oacc[nt][1] };
        *(float2*)&op[rowa * DK + 8 * nt + 2 * gc] = oa;
        float2 ob = { oacc[nt][2], oacc[nt][3] };
        *(float2*)&op[rowb * DK + 8 * nt + 2 * gc] = ob;
    }
    if (gc == 0) {
        g_m[split * NR + rowa] = m_a;
        g_l[split * NR + rowa] = l_a;
        g_m[split * NR + rowb] = m_b;
        g_l[split * NR + rowb] = l_b;
    }
}

// ---------------------------------------------------------------------------
// Combine the NSPLIT partials:  O = (sum_s w_s * O_s) / (sum_s w_s * l_s),
// w_s = exp(m_s - max_s m_s).  One thread per float4 of output.
// ---------------------------------------------------------------------------
__global__ __launch_bounds__(128) void attn_combine_kernel()
{
    int idx = blockIdx.x * 128 + threadIdx.x;   // 0 .. NR*16-1
    int row = idx >> 4;
    int c4  = (idx & 15) << 2;

    float m0 = g_m[0 * NR + row], m1 = g_m[1 * NR + row];
    float m2 = g_m[2 * NR + row], m3 = g_m[3 * NR + row];
    float ms = fmaxf(fmaxf(m0, m1), fmaxf(m2, m3));
    float w0 = __expf(m0 - ms), w1 = __expf(m1 - ms);
    float w2 = __expf(m2 - ms), w3 = __expf(m3 - ms);
    float l  = w0 * g_l[0 * NR + row] + w1 * g_l[1 * NR + row]
             + w2 * g_l[2 * NR + row] + w3 * g_l[3 * NR + row];
    float inv = 1.0f / l;

    size_t off = (size_t)row * DK + c4;
    float4 o0 = *(const float4*)&g_op[0][off];
    float4 o1 = *(const float4*)&g_op[1][off];
    float4 o2 = *(const float4*)&g_op[2][off];
    float4 o3 = *(const float4*)&g_op[3][off];
    float4 o;
    o.x = (w0 * o0.x + w1 * o1.x + w2 * o2.x + w3 * o3.x) * inv;
    o.y = (w0 * o0.y + w1 * o1.y + w2 * o2.y + w3 * o3.y) * inv;
    o.z = (w0 * o0.z + w1 * o1.z + w2 * o2.z + w3 * o3.z) * inv;
    o.w = (w0 * o0.w + w1 * o1.w + w2 * o2.w + w3 * o3.w) * inv;
    *(float4*)&g_att[off] = o;
}

// ---------------------------------------------------------------------------
extern "C" void kernel_launch(void* const* d_in, const int* in_sizes, int n_in,
                              void* d_out, int out_size)
{
    const float* q    = (const float*)d_in[0];
    const float* k    = (const float*)d_in[1];
    const float* v    = (const float*)d_in[2];
    const int*   mask = (const int*)  d_in[3];
    const float* Wq   = (const float*)d_in[4];
    const float* bq   = (const float*)d_in[5];
    const float* Wk   = (const float*)d_in[6];
    const float* bk   = (const float*)d_in[7];
    const float* Wv   = (const float*)d_in[8];
    const float* bv   = (const float*)d_in[9];
    const float* Wo   = (const float*)d_in[10];
    const float* bo   = (const float*)d_in[11];
    float* out = (float*)d_out;

    const int M = BB * SS;  // 16384

    qkv_mma_kernel<<<dim3(M / 64, 3), 128>>>(q, k, v, Wq, bq, Wk, bk, Wv, bv);

    attn_mma_kernel<<<dim3(SS / 64, BB, NSPLIT), 128>>>(mask);
    attn_combine_kernel<<<(NR * 16) / 128, 128>>>();

    outproj_mma_kernel<<<dim3(M / 64, DM / 64), 128>>>(Wo, bo, out);
}

// round 10
// speedup vs baseline: 1.9199x; 1.1161x over previous
#include <cuda_runtime.h>
#include <cstdint>

#define BB 4
#define SS 4096
#define DM 1024
#define DK 64
#define NSPLIT 8
#define SPLITLEN (SS / NSPLIT)   // 512 keys per split
#define NR (BB * SS)             // 16384 rows

// Scratch (device globals per allocation-guard rules)
__device__ float g_qh[BB * SS * DK];
__device__ float g_kh[BB * SS * DK];
__device__ float g_vh[BB * SS * DK];
__device__ float g_att[BB * SS * DK];
__device__ float g_op[NSPLIT][BB * SS * DK];   // unnormalized partial O
__device__ float g_m[NSPLIT * NR];             // per-row running max
__device__ float g_l[NSPLIT * NR];             // per-row running sum

// ---------------------------------------------------------------------------
// tf32 helpers
// ---------------------------------------------------------------------------
__device__ __forceinline__ uint32_t f2tf(float f) {
    uint32_t u;
    asm("cvt.rna.tf32.f32 %0, %1;" : "=r"(u) : "f"(f));
    return u;
}
__device__ __forceinline__ uint32_t tfbits(uint32_t u) {
    uint32_t r;
    asm("cvt.rna.tf32.f32 %0, %1;" : "=r"(r) : "f"(__uint_as_float(u)));
    return r;
}

__device__ __forceinline__ void mma_tf32(float* d, const uint32_t* a,
                                         uint32_t b0, uint32_t b1) {
    asm volatile(
        "mma.sync.aligned.m16n8k8.row.col.f32.tf32.tf32.f32 "
        "{%0,%1,%2,%3}, {%4,%5,%6,%7}, {%8,%9}, {%0,%1,%2,%3};\n"
        : "+f"(d[0]), "+f"(d[1]), "+f"(d[2]), "+f"(d[3])
        : "r"(a[0]), "r"(a[1]), "r"(a[2]), "r"(a[3]), "r"(b0), "r"(b1));
}

__device__ __forceinline__ void cp16(void* s, const void* g) {
    uint32_t sa = (uint32_t)__cvta_generic_to_shared(s);
    asm volatile("cp.async.cg.shared.global [%0], [%1], 16;" :: "r"(sa), "l"(g));
}
__device__ __forceinline__ void cp_commit() {
    asm volatile("cp.async.commit_group;");
}

// ---------------------------------------------------------------------------
// QKV projection via tf32 mma.  X stream: cp.async double-buffered (raw fp32,
// cvt at A-fragment extraction).  W: LDG+cvt+STS (L2-hot, 256x reuse).
// out[m,n] = sum_d X[m,d] * W[n,d] + bias[n].  M=16384, N=64, K=1024.
// Block: 64 rows, 128 threads (4 warps), K-chunks of 64, grid (256, 3).
// ---------------------------------------------------------------------------
#define QKV_XBUF (64 * 68)                         // uint32 per X buffer
#define QKV_SMEM ((2 * QKV_XBUF + 64 * 80) * 4)    // 55296 bytes

__global__ __launch_bounds__(128, 4) void qkv_mma_kernel(
    const float* __restrict__ q, const float* __restrict__ k,
    const float* __restrict__ v,
    const float* __restrict__ Wq, const float* __restrict__ bq,
    const float* __restrict__ Wk, const float* __restrict__ bk,
    const float* __restrict__ Wv, const float* __restrict__ bv)
{
    extern __shared__ uint32_t sq[];
    uint32_t* Xb0 = sq;
    uint32_t* Xb1 = sq + QKV_XBUF;
    uint32_t* Ws  = sq + 2 * QKV_XBUF;

    const int which = blockIdx.y;
    const float* X    = (which == 0) ? q  : (which == 1) ? k  : v;
    const float* W    = (which == 0) ? Wq : (which == 1) ? Wk : Wv;
    const float* bias = (which == 0) ? bq : (which == 1) ? bk : bv;
    float* out        = (which == 0) ? g_qh : (which == 1) ? g_kh : g_vh;

    const int m0   = blockIdx.x * 64;
    const int t    = threadIdx.x;
    const int w    = t >> 5;
    const int lane = t & 31;
    const int gi   = lane >> 2;
    const int gc   = lane & 3;

    const int srow = t >> 4;            // 0..7 staging row base
    const int sc4  = (t & 15) << 2;     // staging col (floats)

    // prologue: cp.async X chunk 0 -> Xb0  (group 0)
    #pragma unroll
    for (int j = 0; j < 8; j++) {
        int row = srow + j * 8;
        cp16(&Xb0[row * 68 + sc4], &X[(size_t)(m0 + row) * DM + sc4]);
    }
    cp_commit();

    float acc[8][4] = {};
    const int ra = 16 * w + gi, rb = ra + 8;

    for (int kc0 = 0; kc0 < 16; kc0++) {
        uint32_t* Xs = (kc0 & 1) ? Xb1 : Xb0;
        const int k0 = kc0 * 64;

        // stage W chunk (LDG + cvt + STS); single buffer, guarded by the
        // end-of-iteration __syncthreads below
        #pragma unroll
        for (int j = 0; j < 8; j++) {
            int f   = t + j * 128;
            int row = f >> 4;
            int c4  = (f & 15) << 2;
            float4 wv = *(const float4*)&W[(size_t)row * DM + k0 + c4];
            uint4  wu = { f2tf(wv.x), f2tf(wv.y), f2tf(wv.z), f2tf(wv.w) };
            *reinterpret_cast<uint4*>(&Ws[row * 80 + c4]) = wu;
        }

        // prefetch next X chunk into the other buffer (group kc0+1)
        if (kc0 + 1 < 16) {
            uint32_t* Xn = (kc0 & 1) ? Xb0 : Xb1;
            int k0n = k0 + 64;
            #pragma unroll
            for (int j = 0; j < 8; j++) {
                int row = srow + j * 8;
                cp16(&Xn[row * 68 + sc4], &X[(size_t)(m0 + row) * DM + k0n + sc4]);
            }
        }
        cp_commit();

        // wait: all groups except the newest (= chunk kc0 is resident)
        asm volatile("cp.async.wait_group 1;");
        __syncthreads();

        // A fragments for this k-chunk (cvt at extraction — raw fp32 in smem)
        uint32_t aq[8][4];
        #pragma unroll
        for (int kc = 0; kc < 4; kc++) {
            int d = 16 * kc + 4 * gc;
            aq[2*kc  ][0] = tfbits(Xs[ra * 68 + d    ]);
            aq[2*kc  ][1] = tfbits(Xs[rb * 68 + d    ]);
            aq[2*kc  ][2] = tfbits(Xs[ra * 68 + d + 1]);
            aq[2*kc  ][3] = tfbits(Xs[rb * 68 + d + 1]);
            aq[2*kc+1][0] = tfbits(Xs[ra * 68 + d + 2]);
            aq[2*kc+1][1] = tfbits(Xs[rb * 68 + d + 2]);
            aq[2*kc+1][2] = tfbits(Xs[ra * 68 + d + 3]);
            aq[2*kc+1][3] = tfbits(Xs[rb * 68 + d + 3]);
        }

        #pragma unroll
        for (int nt = 0; nt < 8; nt++) {
            const uint32_t* kp = Ws + (8 * nt + gi) * 80 + 4 * gc;
            #pragma unroll
            for (int kc = 0; kc < 4; kc++) {
                uint4 bb = *reinterpret_cast<const uint4*>(kp + 16 * kc);
                mma_tf32(acc[nt], aq[2*kc    ], bb.x, bb.y);
                mma_tf32(acc[nt], aq[2*kc + 1], bb.z, bb.w);
            }
        }
        __syncthreads();   // everyone done with Ws / Xs before next overwrite
    }

    #pragma unroll
    for (int nt = 0; nt < 8; nt++) {
        int n = 8 * nt + 2 * gc;
        float2 b2 = *(const float2*)&bias[n];
        float2 oa = { acc[nt][0] + b2.x, acc[nt][1] + b2.y };
        *(float2*)&out[(size_t)(m0 + ra) * DK + n] = oa;
        float2 ob = { acc[nt][2] + b2.x, acc[nt][3] + b2.y };
        *(float2*)&out[(size_t)(m0 + rb) * DK + n] = ob;
    }
}

// ---------------------------------------------------------------------------
// Output projection via tf32 mma.
// ---------------------------------------------------------------------------
__global__ __launch_bounds__(128, 4) void outproj_mma_kernel(const float* __restrict__ Wo,
                                                             const float* __restrict__ bo,
                                                             float* __restrict__ out)
{
    __shared__ uint32_t As[64 * 68];
    __shared__ uint32_t Ws[64 * 80];

    const int m0   = blockIdx.x * 64;
    const int n0   = blockIdx.y * 64;
    const int t    = threadIdx.x;
    const int w    = t >> 5;
    const int lane = t & 31;
    const int gi   = lane >> 2;
    const int gc   = lane & 3;

    #pragma unroll
    for (int j = 0; j < 8; j++) {
        int f   = t + j * 128;
        int row = f >> 4;
        int c4  = (f & 15) << 2;
        float4 av = *(const float4*)&g_att[(size_t)(m0 + row) * DK + c4];
        uint4  au = { f2tf(av.x), f2tf(av.y), f2tf(av.z), f2tf(av.w) };
        *reinterpret_cast<uint4*>(&As[row * 68 + c4]) = au;
        float4 wv = *(const float4*)&Wo[(size_t)(n0 + row) * DK + c4];
        uint4  wu = { f2tf(wv.x), f2tf(wv.y), f2tf(wv.z), f2tf(wv.w) };
        *reinterpret_cast<uint4*>(&Ws[row * 80 + c4]) = wu;
    }
    __syncthreads();

    const int ra = 16 * w + gi, rb = ra + 8;

    uint32_t aq[8][4];
    #pragma unroll
    for (int kc = 0; kc < 4; kc++) {
        int d = 16 * kc + 4 * gc;
        aq[2*kc  ][0] = As[ra * 68 + d    ];
        aq[2*kc  ][1] = As[rb * 68 + d    ];
        aq[2*kc  ][2] = As[ra * 68 + d + 1];
        aq[2*kc  ][3] = As[rb * 68 + d + 1];
        aq[2*kc+1][0] = As[ra * 68 + d + 2];
        aq[2*kc+1][1] = As[rb * 68 + d + 2];
        aq[2*kc+1][2] = As[ra * 68 + d + 3];
        aq[2*kc+1][3] = As[rb * 68 + d + 3];
    }

    float acc[8][4] = {};
    #pragma unroll
    for (int nt = 0; nt < 8; nt++) {
        const uint32_t* kp = Ws + (8 * nt + gi) * 80 + 4 * gc;
        #pragma unroll
        for (int kc = 0; kc < 4; kc++) {
            uint4 bb = *reinterpret_cast<const uint4*>(kp + 16 * kc);
            mma_tf32(acc[nt], aq[2*kc    ], bb.x, bb.y);
            mma_tf32(acc[nt], aq[2*kc + 1], bb.z, bb.w);
        }
    }

    #pragma unroll
    for (int nt = 0; nt < 8; nt++) {
        int n = n0 + 8 * nt + 2 * gc;
        float2 b2 = *(const float2*)&bo[n];
        float2 oa = { acc[nt][0] + b2.x, acc[nt][1] + b2.y };
        *(float2*)&out[(size_t)(m0 + ra) * DM + n] = oa;
        float2 ob = { acc[nt][2] + b2.x, acc[nt][3] + b2.y };
        *(float2*)&out[(size_t)(m0 + rb) * DM + n] = ob;
    }
}

// ---------------------------------------------------------------------------
// Split-K flash attention.  Grid (SS/64, BB, NSPLIT) = 2048 blocks.
// Each block: 64 queries x 512 keys (8 tiles).  Writes unnormalized O
// partial + per-row (m, l); combine kernel merges the 8 splits.
// ---------------------------------------------------------------------------
#define KSTR 80
#define VSTR 84

__global__ __launch_bounds__(128, 4) void attn_mma_kernel(const int* __restrict__ mask)
{
    __shared__ float sbuf[64 * KSTR + 64 * VSTR];   // 41984 B
    float* Ks = sbuf;                // [64][KSTR]
    float* Vs = sbuf + 64 * KSTR;    // [64][VSTR]
    float* Qs = sbuf;                // staging overlay [64][68]

    const int b     = blockIdx.y;
    const int q0    = blockIdx.x * 64;
    const int split = blockIdx.z;
    const int t     = threadIdx.x;
    const int w     = t >> 5;          // 0..3
    const int lane  = t & 31;
    const int gi    = lane >> 2;
    const int gc    = lane & 3;
    const float scale = 0.125f;        // 1/sqrt(64)

    // ---- stage Q through smem, extract resident A-fragments ----
    const float* qh = g_qh + ((size_t)b * SS + q0) * DK;
    #pragma unroll
    for (int j = 0; j < 8; j++) {
        int f   = t + j * 128;        // 0..1023
        int row = f >> 4;
        int c4  = (f & 15) << 2;
        *(float4*)&Qs[row * 68 + c4] = *(const float4*)&qh[row * DK + c4];
    }
    __syncthreads();

    uint32_t aq[8][4];
    {
        int ra = 16 * w + gi, rb = ra + 8;
        #pragma unroll
        for (int kc = 0; kc < 4; kc++) {
            int d = 16 * kc + 4 * gc;
            aq[2*kc  ][0] = f2tf(Qs[ra * 68 + d    ]);
            aq[2*kc  ][1] = f2tf(Qs[rb * 68 + d    ]);
            aq[2*kc  ][2] = f2tf(Qs[ra * 68 + d + 1]);
            aq[2*kc  ][3] = f2tf(Qs[rb * 68 + d + 1]);
            aq[2*kc+1][0] = f2tf(Qs[ra * 68 + d + 2]);
            aq[2*kc+1][1] = f2tf(Qs[rb * 68 + d + 2]);
            aq[2*kc+1][2] = f2tf(Qs[ra * 68 + d + 3]);
            aq[2*kc+1][3] = f2tf(Qs[rb * 68 + d + 3]);
        }
    }
    __syncthreads();   // everyone done reading Q before Ks overwrites it

    float oacc[8][4] = {};
    float m_a = -1e30f, m_b = -1e30f, l_a = 0.0f, l_b = 0.0f;

    const int qa = q0 + 16 * w + gi;     // row within batch (0..4095)
    const int qb = qa + 8;

    const float* khb = g_kh + (size_t)b * SS * DK;
    const float* vhb = g_vh + (size_t)b * SS * DK;
    const int2* mrow_a = (const int2*)(mask + (size_t)qa * SS);
    const int2* mrow_b = (const int2*)(mask + (size_t)qb * SS);

    const int kbeg = split * SPLITLEN;
    const int kend = kbeg + SPLITLEN;

    for (int kt = kbeg; kt < kend; kt += 64) {
        // ---- stage K, V tiles (cvt to tf32 at store) ----
        #pragma unroll
        for (int j = 0; j < 8; j++) {
            int f   = t + j * 128;      // 0..1023
            int key = f >> 4;
            int c4  = (f & 15) << 2;
            float4 kv = *(const float4*)&khb[(size_t)(kt + key) * DK + c4];
            uint4  ku = { f2tf(kv.x), f2tf(kv.y), f2tf(kv.z), f2tf(kv.w) };
            *reinterpret_cast<uint4*>(Ks + key * KSTR + c4) = ku;
            float4 vv = *(const float4*)&vhb[(size_t)(kt + key) * DK + c4];
            uint4  vu = { f2tf(vv.x), f2tf(vv.y), f2tf(vv.z), f2tf(vv.w) };
            *reinterpret_cast<uint4*>(Vs + key * VSTR + c4) = vu;
        }
        __syncthreads();

        // ---- GEMM1: S = Q . K^T ----
        float sacc[8][4];
        #pragma unroll
        for (int nt = 0; nt < 8; nt++) {
            sacc[nt][0] = 0.f; sacc[nt][1] = 0.f;
            sacc[nt][2] = 0.f; sacc[nt][3] = 0.f;
        }
        #pragma unroll
        for (int nt = 0; nt < 8; nt++) {
            const float* kp = Ks + (8 * nt + gi) * KSTR + 4 * gc;
            #pragma unroll
            for (int kc = 0; kc < 4; kc++) {
                uint4 bb = *reinterpret_cast<const uint4*>(kp + 16 * kc);
                mma_tf32(sacc[nt], aq[2*kc    ], bb.x, bb.y);
                mma_tf32(sacc[nt], aq[2*kc + 1], bb.z, bb.w);
            }
        }

        // ---- scale + mask ----
        const int mbase = (kt >> 1) + gc;
        #pragma unroll
        for (int nt = 0; nt < 8; nt++) {
            int2 ma = mrow_a[mbase + 4 * nt];
            int2 mb = mrow_b[mbase + 4 * nt];
            sacc[nt][0] = ma.x ? sacc[nt][0] * scale : -1e9f;
            sacc[nt][1] = ma.y ? sacc[nt][1] * scale : -1e9f;
            sacc[nt][2] = mb.x ? sacc[nt][2] * scale : -1e9f;
            sacc[nt][3] = mb.y ? sacc[nt][3] * scale : -1e9f;
        }

        // ---- online softmax ----
        float mxa = -1e30f, mxb = -1e30f;
        #pragma unroll
        for (int nt = 0; nt < 8; nt++) {
            mxa = fmaxf(mxa, fmaxf(sacc[nt][0], sacc[nt][1]));
            mxb = fmaxf(mxb, fmaxf(sacc[nt][2], sacc[nt][3]));
        }
        mxa = fmaxf(mxa, __shfl_xor_sync(0xffffffffu, mxa, 1));
        mxa = fmaxf(mxa, __shfl_xor_sync(0xffffffffu, mxa, 2));
        mxb = fmaxf(mxb, __shfl_xor_sync(0xffffffffu, mxb, 1));
        mxb = fmaxf(mxb, __shfl_xor_sync(0xffffffffu, mxb, 2));

        float mna = fmaxf(m_a, mxa);
        float mnb = fmaxf(m_b, mxb);
        float ca = __expf(m_a - mna);  m_a = mna;
        float cb = __expf(m_b - mnb);  m_b = mnb;

        // ---- P = exp(S - m) in place (tf32, permuted (c0,c2,c1,c3)) ----
        float sla = 0.0f, slb = 0.0f;
        #pragma unroll
        for (int nt = 0; nt < 8; nt++) {
            float p0 = __expf(sacc[nt][0] - m_a);
            float p1 = __expf(sacc[nt][1] - m_a);
            float p2 = __expf(sacc[nt][2] - m_b);
            float p3 = __expf(sacc[nt][3] - m_b);
            sla += p0 + p1;
            slb += p2 + p3;
            sacc[nt][0] = __uint_as_float(f2tf(p0));
            sacc[nt][1] = __uint_as_float(f2tf(p2));
            sacc[nt][2] = __uint_as_float(f2tf(p1));
            sacc[nt][3] = __uint_as_float(f2tf(p3));
        }
        sla += __shfl_xor_sync(0xffffffffu, sla, 1);
        sla += __shfl_xor_sync(0xffffffffu, sla, 2);
        slb += __shfl_xor_sync(0xffffffffu, slb, 1);
        slb += __shfl_xor_sync(0xffffffffu, slb, 2);
        l_a = l_a * ca + sla;
        l_b = l_b * cb + slb;

        #pragma unroll
        for (int nt = 0; nt < 8; nt++) {
            oacc[nt][0] *= ca; oacc[nt][1] *= ca;
            oacc[nt][2] *= cb; oacc[nt][3] *= cb;
        }

        // ---- GEMM2: O += P . V ----
        #pragma unroll
        for (int nt = 0; nt < 8; nt++) {
            const float* vp = Vs + 8 * nt + gi;     // dv column base
            #pragma unroll
            for (int g = 0; g < 8; g++) {
                uint32_t b0 = *reinterpret_cast<const uint32_t*>(
                                  vp + (8 * g + 2 * gc)     * VSTR);
                uint32_t b1 = *reinterpret_cast<const uint32_t*>(
                                  vp + (8 * g + 2 * gc + 1) * VSTR);
                mma_tf32(oacc[nt], reinterpret_cast<const uint32_t*>(sacc[g]),
                         b0, b1);
            }
        }
        __syncthreads();   // tiles consumed; safe to overwrite next iteration
    }

    // ---- write unnormalized partial O + (m, l) ----
    const size_t rowa = (size_t)b * SS + qa;
    const size_t rowb = (size_t)b * SS + qb;
    float* op = g_op[split];
    #pragma unroll
    for (int nt = 0; nt < 8; nt++) {
        float2 oa = { oacc[nt][0], oacc[nt][1] };
        *(float2*)&op[rowa * DK + 8 * nt + 2 * gc] = oa;
        float2 ob = { oacc[nt][2], oacc[nt][3] };
        *(float2*)&op[rowb * DK + 8 * nt + 2 * gc] = ob;
    }
    if (gc == 0) {
        g_m[split * NR + rowa] = m_a;
        g_l[split * NR + rowa] = l_a;
        g_m[split * NR + rowb] = m_b;
        g_l[split * NR + rowb] = l_b;
    }
}

// ---------------------------------------------------------------------------
// Combine the NSPLIT partials:  O = (sum_s w_s * O_s) / (sum_s w_s * l_s),
// w_s = exp(m_s - max_s m_s).  One thread per float4 of output.
// ---------------------------------------------------------------------------
__global__ __launch_bounds__(128) void attn_combine_kernel()
{
    int idx = blockIdx.x * 128 + threadIdx.x;   // 0 .. NR*16-1
    int row = idx >> 4;
    int c4  = (idx & 15) << 2;

    float m[NSPLIT], wgt[NSPLIT];
    float ms = -1e30f;
    #pragma unroll
    for (int s = 0; s < NSPLIT; s++) {
        m[s] = g_m[s * NR + row];
        ms = fmaxf(ms, m[s]);
    }
    float lsum = 0.0f;
    #pragma unroll
    for (int s = 0; s < NSPLIT; s++) {
        wgt[s] = __expf(m[s] - ms);
        lsum += wgt[s] * g_l[s * NR + row];
    }
    float inv = 1.0f / lsum;

    size_t off = (size_t)row * DK + c4;
    float4 o = { 0.f, 0.f, 0.f, 0.f };
    #pragma unroll
    for (int s = 0; s < NSPLIT; s++) {
        float4 p = *(const float4*)&g_op[s][off];
        o.x += wgt[s] * p.x;  o.y += wgt[s] * p.y;
        o.z += wgt[s] * p.z;  o.w += wgt[s] * p.w;
    }
    o.x *= inv; o.y *= inv; o.z *= inv; o.w *= inv;
    *(float4*)&g_att[off] = o;
}

// ---------------------------------------------------------------------------
extern "C" void kernel_launch(void* const* d_in, const int* in_sizes, int n_in,
                              void* d_out, int out_size)
{
    const float* q    = (const float*)d_in[0];
    const float* k    = (const float*)d_in[1];
    const float* v    = (const float*)d_in[2];
    const int*   mask = (const int*)  d_in[3];
    const float* Wq   = (const float*)d_in[4];
    const float* bq   = (const float*)d_in[5];
    const float* Wk   = (const float*)d_in[6];
    const float* bk   = (const float*)d_in[7];
    const float* Wv   = (const float*)d_in[8];
    const float* bv   = (const float*)d_in[9];
    const float* Wo   = (const float*)d_in[10];
    const float* bo   = (const float*)d_in[11];
    float* out = (float*)d_out;

    cudaFuncSetAttribute(qkv_mma_kernel,
                         cudaFuncAttributeMaxDynamicSharedMemorySize, QKV_SMEM);

    const int M = BB * SS;  // 16384

    qkv_mma_kernel<<<dim3(M / 64, 3), 128, QKV_SMEM>>>(q, k, v,
                                                       Wq, bq, Wk, bk, Wv, bv);

    attn_mma_kernel<<<dim3(SS / 64, BB, NSPLIT), 128>>>(mask);
    attn_combine_kernel<<<(NR * 16) / 128, 128>>>();

    outproj_mma_kernel<<<dim3(M / 64, DM / 64), 128>>>(Wo, bo, out);
}

// round 11
// speedup vs baseline: 2.7093x; 1.4112x over previous
#include <cuda_runtime.h>
#include <cuda_fp16.h>
#include <cstdint>

#define BB 4
#define SS 4096
#define DM 1024
#define DK 64
#define NSPLIT 8
#define SPLITLEN (SS / NSPLIT)   // 512 keys per split
#define NR (BB * SS)             // 16384 rows

// Scratch (device globals per allocation-guard rules)
__device__ __half g_qh[BB * SS * DK];          // fp16 Q  [token][d]
__device__ __half g_kh[BB * SS * DK];          // fp16 K  [token][d]
__device__ __half g_vt[BB * DK * SS];          // fp16 V^T [b][dv][token]
__device__ float  g_att[BB * SS * DK];
__device__ float  g_op[NSPLIT][BB * SS * DK];  // unnormalized partial O
__device__ float  g_m[NSPLIT * NR];
__device__ float  g_l[NSPLIT * NR];

// ---------------------------------------------------------------------------
// helpers
// ---------------------------------------------------------------------------
__device__ __forceinline__ uint32_t f2tf(float f) {
    uint32_t u;
    asm("cvt.rna.tf32.f32 %0, %1;" : "=r"(u) : "f"(f));
    return u;
}
__device__ __forceinline__ uint32_t tfbits(uint32_t u) {
    uint32_t r;
    asm("cvt.rna.tf32.f32 %0, %1;" : "=r"(r) : "f"(__uint_as_float(u)));
    return r;
}
// pack two fp32 -> f16x2  (lo = first arg, hi = second arg)
__device__ __forceinline__ uint32_t pack_h2(float lo, float hi) {
    uint32_t r;
    asm("cvt.rn.f16x2.f32 %0, %1, %2;" : "=r"(r) : "f"(hi), "f"(lo));
    return r;
}

__device__ __forceinline__ void mma_tf32(float* d, const uint32_t* a,
                                         uint32_t b0, uint32_t b1) {
    asm volatile(
        "mma.sync.aligned.m16n8k8.row.col.f32.tf32.tf32.f32 "
        "{%0,%1,%2,%3}, {%4,%5,%6,%7}, {%8,%9}, {%0,%1,%2,%3};\n"
        : "+f"(d[0]), "+f"(d[1]), "+f"(d[2]), "+f"(d[3])
        : "r"(a[0]), "r"(a[1]), "r"(a[2]), "r"(a[3]), "r"(b0), "r"(b1));
}

__device__ __forceinline__ void mma_f16(float* d, const uint32_t* a,
                                        uint32_t b0, uint32_t b1) {
    asm volatile(
        "mma.sync.aligned.m16n8k16.row.col.f32.f16.f16.f32 "
        "{%0,%1,%2,%3}, {%4,%5,%6,%7}, {%8,%9}, {%0,%1,%2,%3};\n"
        : "+f"(d[0]), "+f"(d[1]), "+f"(d[2]), "+f"(d[3])
        : "r"(a[0]), "r"(a[1]), "r"(a[2]), "r"(a[3]), "r"(b0), "r"(b1));
}

__device__ __forceinline__ void cp16(void* s, const void* g) {
    uint32_t sa = (uint32_t)__cvta_generic_to_shared(s);
    asm volatile("cp.async.cg.shared.global [%0], [%1], 16;" :: "r"(sa), "l"(g));
}
__device__ __forceinline__ void cp_commit() {
    asm volatile("cp.async.commit_group;");
}

// ---------------------------------------------------------------------------
// QKV projection via tf32 mma (mainloop unchanged from R9).
// Epilogue now writes fp16: Q/K as [token][d], V transposed [b][dv][token].
// ---------------------------------------------------------------------------
#define QKV_XBUF (64 * 68)                         // uint32 per X buffer
#define QKV_SMEM ((2 * QKV_XBUF + 64 * 80) * 4)    // 55296 bytes

__global__ __launch_bounds__(128, 4) void qkv_mma_kernel(
    const float* __restrict__ q, const float* __restrict__ k,
    const float* __restrict__ v,
    const float* __restrict__ Wq, const float* __restrict__ bq,
    const float* __restrict__ Wk, const float* __restrict__ bk,
    const float* __restrict__ Wv, const float* __restrict__ bv)
{
    extern __shared__ uint32_t sq[];
    uint32_t* Xb0 = sq;
    uint32_t* Xb1 = sq + QKV_XBUF;
    uint32_t* Ws  = sq + 2 * QKV_XBUF;

    const int which = blockIdx.y;
    const float* X    = (which == 0) ? q  : (which == 1) ? k  : v;
    const float* W    = (which == 0) ? Wq : (which == 1) ? Wk : Wv;
    const float* bias = (which == 0) ? bq : (which == 1) ? bk : bv;

    const int m0   = blockIdx.x * 64;
    const int t    = threadIdx.x;
    const int w    = t >> 5;
    const int lane = t & 31;
    const int gi   = lane >> 2;
    const int gc   = lane & 3;

    const int srow = t >> 4;
    const int sc4  = (t & 15) << 2;

    #pragma unroll
    for (int j = 0; j < 8; j++) {
        int row = srow + j * 8;
        cp16(&Xb0[row * 68 + sc4], &X[(size_t)(m0 + row) * DM + sc4]);
    }
    cp_commit();

    float acc[8][4] = {};
    const int ra = 16 * w + gi, rb = ra + 8;

    for (int kc0 = 0; kc0 < 16; kc0++) {
        uint32_t* Xs = (kc0 & 1) ? Xb1 : Xb0;
        const int k0 = kc0 * 64;

        #pragma unroll
        for (int j = 0; j < 8; j++) {
            int f   = t + j * 128;
            int row = f >> 4;
            int c4  = (f & 15) << 2;
            float4 wv = *(const float4*)&W[(size_t)row * DM + k0 + c4];
            uint4  wu = { f2tf(wv.x), f2tf(wv.y), f2tf(wv.z), f2tf(wv.w) };
            *reinterpret_cast<uint4*>(&Ws[row * 80 + c4]) = wu;
        }

        if (kc0 + 1 < 16) {
            uint32_t* Xn = (kc0 & 1) ? Xb0 : Xb1;
            int k0n = k0 + 64;
            #pragma unroll
            for (int j = 0; j < 8; j++) {
                int row = srow + j * 8;
                cp16(&Xn[row * 68 + sc4], &X[(size_t)(m0 + row) * DM + k0n + sc4]);
            }
        }
        cp_commit();

        asm volatile("cp.async.wait_group 1;");
        __syncthreads();

        uint32_t aq[8][4];
        #pragma unroll
        for (int kc = 0; kc < 4; kc++) {
            int d = 16 * kc + 4 * gc;
            aq[2*kc  ][0] = tfbits(Xs[ra * 68 + d    ]);
            aq[2*kc  ][1] = tfbits(Xs[rb * 68 + d    ]);
            aq[2*kc  ][2] = tfbits(Xs[ra * 68 + d + 1]);
            aq[2*kc  ][3] = tfbits(Xs[rb * 68 + d + 1]);
            aq[2*kc+1][0] = tfbits(Xs[ra * 68 + d + 2]);
            aq[2*kc+1][1] = tfbits(Xs[rb * 68 + d + 2]);
            aq[2*kc+1][2] = tfbits(Xs[ra * 68 + d + 3]);
            aq[2*kc+1][3] = tfbits(Xs[rb * 68 + d + 3]);
        }

        #pragma unroll
        for (int nt = 0; nt < 8; nt++) {
            const uint32_t* kp = Ws + (8 * nt + gi) * 80 + 4 * gc;
            #pragma unroll
            for (int kc = 0; kc < 4; kc++) {
                uint4 bb = *reinterpret_cast<const uint4*>(kp + 16 * kc);
                mma_tf32(acc[nt], aq[2*kc    ], bb.x, bb.y);
                mma_tf32(acc[nt], aq[2*kc + 1], bb.z, bb.w);
            }
        }
        __syncthreads();
    }

    if (which != 2) {
        __half* outh = (which == 0) ? g_qh : g_kh;
        #pragma unroll
        for (int nt = 0; nt < 8; nt++) {
            int n = 8 * nt + 2 * gc;
            float2 b2 = *(const float2*)&bias[n];
            uint32_t ha = pack_h2(acc[nt][0] + b2.x, acc[nt][1] + b2.y);
            *(uint32_t*)&outh[(size_t)(m0 + ra) * DK + n] = ha;
            uint32_t hb = pack_h2(acc[nt][2] + b2.x, acc[nt][3] + b2.y);
            *(uint32_t*)&outh[(size_t)(m0 + rb) * DK + n] = hb;
        }
    } else {
        // V transposed: g_vt[b][dv][token]  (64-row blocks never straddle batch)
        int bidx = (m0 + ra) >> 12;
        int sa   = (m0 + ra) & (SS - 1);
        int sb   = (m0 + rb) & (SS - 1);
        __half* vt = g_vt + (size_t)bidx * DK * SS;
        #pragma unroll
        for (int nt = 0; nt < 8; nt++) {
            int n = 8 * nt + 2 * gc;
            float2 b2 = *(const float2*)&bias[n];
            vt[(size_t)(n    ) * SS + sa] = __float2half_rn(acc[nt][0] + b2.x);
            vt[(size_t)(n + 1) * SS + sa] = __float2half_rn(acc[nt][1] + b2.y);
            vt[(size_t)(n    ) * SS + sb] = __float2half_rn(acc[nt][2] + b2.x);
            vt[(size_t)(n + 1) * SS + sb] = __float2half_rn(acc[nt][3] + b2.y);
        }
    }
}

// ---------------------------------------------------------------------------
// Output projection via tf32 mma.  A-tile staged once, reused for 4 n-tiles.
// Grid (256, 4): block = 64 rows x 256 cols.
// ---------------------------------------------------------------------------
__global__ __launch_bounds__(128, 4) void outproj_mma_kernel(const float* __restrict__ Wo,
                                                             const float* __restrict__ bo,
                                                             float* __restrict__ out)
{
    __shared__ uint32_t As[64 * 68];
    __shared__ uint32_t Ws[64 * 80];

    const int m0   = blockIdx.x * 64;
    const int n00  = blockIdx.y * 256;
    const int t    = threadIdx.x;
    const int w    = t >> 5;
    const int lane = t & 31;
    const int gi   = lane >> 2;
    const int gc   = lane & 3;

    // stage A tile once
    #pragma unroll
    for (int j = 0; j < 8; j++) {
        int f   = t + j * 128;
        int row = f >> 4;
        int c4  = (f & 15) << 2;
        float4 av = *(const float4*)&g_att[(size_t)(m0 + row) * DK + c4];
        uint4  au = { f2tf(av.x), f2tf(av.y), f2tf(av.z), f2tf(av.w) };
        *reinterpret_cast<uint4*>(&As[row * 68 + c4]) = au;
    }

    const int ra = 16 * w + gi, rb = ra + 8;
    uint32_t aq[8][4];
    bool aq_done = false;

    for (int ny = 0; ny < 4; ny++) {
        const int n0 = n00 + 64 * ny;

        #pragma unroll
        for (int j = 0; j < 8; j++) {
            int f   = t + j * 128;
            int row = f >> 4;
            int c4  = (f & 15) << 2;
            float4 wv = *(const float4*)&Wo[(size_t)(n0 + row) * DK + c4];
            uint4  wu = { f2tf(wv.x), f2tf(wv.y), f2tf(wv.z), f2tf(wv.w) };
            *reinterpret_cast<uint4*>(&Ws[row * 80 + c4]) = wu;
        }
        __syncthreads();

        if (!aq_done) {
            aq_done = true;
            #pragma unroll
            for (int kc = 0; kc < 4; kc++) {
                int d = 16 * kc + 4 * gc;
                aq[2*kc  ][0] = As[ra * 68 + d    ];
                aq[2*kc  ][1] = As[rb * 68 + d    ];
                aq[2*kc  ][2] = As[ra * 68 + d + 1];
                aq[2*kc  ][3] = As[rb * 68 + d + 1];
                aq[2*kc+1][0] = As[ra * 68 + d + 2];
                aq[2*kc+1][1] = As[rb * 68 + d + 2];
                aq[2*kc+1][2] = As[ra * 68 + d + 3];
                aq[2*kc+1][3] = As[rb * 68 + d + 3];
            }
        }

        float acc[8][4] = {};
        #pragma unroll
        for (int nt = 0; nt < 8; nt++) {
            const uint32_t* kp = Ws + (8 * nt + gi) * 80 + 4 * gc;
            #pragma unroll
            for (int kc = 0; kc < 4; kc++) {
                uint4 bb = *reinterpret_cast<const uint4*>(kp + 16 * kc);
                mma_tf32(acc[nt], aq[2*kc    ], bb.x, bb.y);
                mma_tf32(acc[nt], aq[2*kc + 1], bb.z, bb.w);
            }
        }

        #pragma unroll
        for (int nt = 0; nt < 8; nt++) {
            int n = n0 + 8 * nt + 2 * gc;
            float2 b2 = *(const float2*)&bo[n];
            float2 oa = { acc[nt][0] + b2.x, acc[nt][1] + b2.y };
            *(float2*)&out[(size_t)(m0 + ra) * DM + n] = oa;
            float2 ob = { acc[nt][2] + b2.x, acc[nt][3] + b2.y };
            *(float2*)&out[(size_t)(m0 + rb) * DM + n] = ob;
        }
        __syncthreads();
    }
}

// ---------------------------------------------------------------------------
// Split-K flash attention, fp16 mma (m16n8k16, fp32 accumulate).
// Grid (SS/64, BB, NSPLIT) = 2048 blocks, 128 threads.
// K tile [key][72] halves, V^T tile [dv][72] halves — conflict-free LDS.32.
// ---------------------------------------------------------------------------
#define HSTR 72   // halfword stride for K / Vt / Q smem tiles

__global__ __launch_bounds__(128, 4) void attn_mma_kernel(const int* __restrict__ mask)
{
    __shared__ __half sh[64 * HSTR * 2];   // 18432 B
    __half* Ks  = sh;                 // [64 keys][HSTR]
    __half* Vts = sh + 64 * HSTR;     // [64 dv][HSTR]
    __half* Qs  = sh;                 // staging overlay [64 rows][HSTR]

    const int b     = blockIdx.y;
    const int q0    = blockIdx.x * 64;
    const int split = blockIdx.z;
    const int t     = threadIdx.x;
    const int w     = t >> 5;
    const int lane  = t & 31;
    const int gi    = lane >> 2;
    const int gc    = lane & 3;
    const float scale = 0.125f;

    const int ra = 16 * w + gi, rb = ra + 8;

    // ---- stage Q (fp16) and extract A fragments ----
    const __half* qh = g_qh + ((size_t)b * SS + q0) * DK;
    #pragma unroll
    for (int j = 0; j < 4; j++) {
        int f   = t + j * 128;        // 0..511
        int row = f >> 3;
        int dg  = (f & 7) << 3;       // halfword offset, multiple of 8
        *reinterpret_cast<uint4*>(&Qs[row * HSTR + dg]) =
            *reinterpret_cast<const uint4*>(&qh[row * DK + dg]);
    }
    __syncthreads();

    uint32_t aq[4][4];
    #pragma unroll
    for (int kc = 0; kc < 4; kc++) {
        int d = 16 * kc + 2 * gc;
        aq[kc][0] = *(const uint32_t*)&Qs[ra * HSTR + d    ];
        aq[kc][1] = *(const uint32_t*)&Qs[rb * HSTR + d    ];
        aq[kc][2] = *(const uint32_t*)&Qs[ra * HSTR + d + 8];
        aq[kc][3] = *(const uint32_t*)&Qs[rb * HSTR + d + 8];
    }
    __syncthreads();

    float oacc[8][4] = {};
    float m_a = -1e30f, m_b = -1e30f, l_a = 0.0f, l_b = 0.0f;

    const int qa = q0 + ra;
    const int qb = q0 + rb;

    const __half* khb = g_kh + (size_t)b * SS * DK;
    const __half* vtb = g_vt + (size_t)b * DK * SS;
    const int2* mrow_a = (const int2*)(mask + (size_t)qa * SS);
    const int2* mrow_b = (const int2*)(mask + (size_t)qb * SS);

    const int kbeg = split * SPLITLEN;
    const int kend = kbeg + SPLITLEN;

    for (int kt = kbeg; kt < kend; kt += 64) {
        // ---- stage K [key][d] and V^T [dv][key] (straight fp16 copies) ----
        #pragma unroll
        for (int j = 0; j < 4; j++) {
            int f   = t + j * 128;
            int r   = f >> 3;
            int dg  = (f & 7) << 3;
            *reinterpret_cast<uint4*>(&Ks[r * HSTR + dg]) =
                *reinterpret_cast<const uint4*>(&khb[(size_t)(kt + r) * DK + dg]);
            *reinterpret_cast<uint4*>(&Vts[r * HSTR + dg]) =
                *reinterpret_cast<const uint4*>(&vtb[(size_t)r * SS + kt + dg]);
        }
        __syncthreads();

        // ---- GEMM1: S = Q . K^T  (fp16, K=16 per mma) ----
        float sacc[8][4];
        #pragma unroll
        for (int nt = 0; nt < 8; nt++) {
            sacc[nt][0] = 0.f; sacc[nt][1] = 0.f;
            sacc[nt][2] = 0.f; sacc[nt][3] = 0.f;
        }
        #pragma unroll
        for (int nt = 0; nt < 8; nt++) {
            const __half* kp = Ks + (8 * nt + gi) * HSTR + 2 * gc;
            #pragma unroll
            for (int kc = 0; kc < 4; kc++) {
                uint32_t b0 = *(const uint32_t*)&kp[16 * kc    ];
                uint32_t b1 = *(const uint32_t*)&kp[16 * kc + 8];
                mma_f16(sacc[nt], aq[kc], b0, b1);
            }
        }

        // ---- scale + mask ----
        const int mbase = (kt >> 1) + gc;
        #pragma unroll
        for (int nt = 0; nt < 8; nt++) {
            int2 ma = mrow_a[mbase + 4 * nt];
            int2 mb = mrow_b[mbase + 4 * nt];
            sacc[nt][0] = ma.x ? sacc[nt][0] * scale : -1e9f;
            sacc[nt][1] = ma.y ? sacc[nt][1] * scale : -1e9f;
            sacc[nt][2] = mb.x ? sacc[nt][2] * scale : -1e9f;
            sacc[nt][3] = mb.y ? sacc[nt][3] * scale : -1e9f;
        }

        // ---- online softmax ----
        float mxa = -1e30f, mxb = -1e30f;
        #pragma unroll
        for (int nt = 0; nt < 8; nt++) {
            mxa = fmaxf(mxa, fmaxf(sacc[nt][0], sacc[nt][1]));
            mxb = fmaxf(mxb, fmaxf(sacc[nt][2], sacc[nt][3]));
        }
        mxa = fmaxf(mxa, __shfl_xor_sync(0xffffffffu, mxa, 1));
        mxa = fmaxf(mxa, __shfl_xor_sync(0xffffffffu, mxa, 2));
        mxb = fmaxf(mxb, __shfl_xor_sync(0xffffffffu, mxb, 1));
        mxb = fmaxf(mxb, __shfl_xor_sync(0xffffffffu, mxb, 2));

        float mna = fmaxf(m_a, mxa);
        float mnb = fmaxf(m_b, mxb);
        float ca = __expf(m_a - mna);  m_a = mna;
        float cb = __expf(m_b - mnb);  m_b = mnb;

        // ---- P = exp(S-m), packed straight into f16 A-fragments ----
        // chunk g (16 keys) uses nt=2g (a0,a1) and nt=2g+1 (a2,a3)
        uint32_t pa[4][4];
        float sla = 0.0f, slb = 0.0f;
        #pragma unroll
        for (int nt = 0; nt < 8; nt++) {
            float p0 = __expf(sacc[nt][0] - m_a);
            float p1 = __expf(sacc[nt][1] - m_a);
            float p2 = __expf(sacc[nt][2] - m_b);
            float p3 = __expf(sacc[nt][3] - m_b);
            sla += p0 + p1;
            slb += p2 + p3;
            int g = nt >> 1;
            int h = (nt & 1) << 1;
            pa[g][h    ] = pack_h2(p0, p1);   // row a, key pair
            pa[g][h + 1] = pack_h2(p2, p3);   // row b, key pair
        }
        sla += __shfl_xor_sync(0xffffffffu, sla, 1);
        sla += __shfl_xor_sync(0xffffffffu, sla, 2);
        slb += __shfl_xor_sync(0xffffffffu, slb, 1);
        slb += __shfl_xor_sync(0xffffffffu, slb, 2);
        l_a = l_a * ca + sla;
        l_b = l_b * cb + slb;

        #pragma unroll
        for (int nt = 0; nt < 8; nt++) {
            oacc[nt][0] *= ca; oacc[nt][1] *= ca;
            oacc[nt][2] *= cb; oacc[nt][3] *= cb;
        }

        // ---- GEMM2: O += P . V  (B from V^T tile) ----
        #pragma unroll
        for (int nt = 0; nt < 8; nt++) {
            const __half* vp = Vts + (8 * nt + gi) * HSTR + 2 * gc;
            #pragma unroll
            for (int g = 0; g < 4; g++) {
                uint32_t b0 = *(const uint32_t*)&vp[16 * g    ];
                uint32_t b1 = *(const uint32_t*)&vp[16 * g + 8];
                mma_f16(oacc[nt], pa[g], b0, b1);
            }
        }
        __syncthreads();
    }

    // ---- write unnormalized partial O + (m, l) ----
    const size_t rowa = (size_t)b * SS + qa;
    const size_t rowb = (size_t)b * SS + qb;
    float* op = g_op[split];
    #pragma unroll
    for (int nt = 0; nt < 8; nt++) {
        float2 oa = { oacc[nt][0], oacc[nt][1] };
        *(float2*)&op[rowa * DK + 8 * nt + 2 * gc] = oa;
        float2 ob = { oacc[nt][2], oacc[nt][3] };
        *(float2*)&op[rowb * DK + 8 * nt + 2 * gc] = ob;
    }
    if (gc == 0) {
        g_m[split * NR + rowa] = m_a;
        g_l[split * NR + rowa] = l_a;
        g_m[split * NR + rowb] = m_b;
        g_l[split * NR + rowb] = l_b;
    }
}

// ---------------------------------------------------------------------------
// Combine the NSPLIT partials.
// ---------------------------------------------------------------------------
__global__ __launch_bounds__(128) void attn_combine_kernel()
{
    int idx = blockIdx.x * 128 + threadIdx.x;
    int row = idx >> 4;
    int c4  = (idx & 15) << 2;

    float m[NSPLIT], wgt[NSPLIT];
    float ms = -1e30f;
    #pragma unroll
    for (int s = 0; s < NSPLIT; s++) {
        m[s] = g_m[s * NR + row];
        ms = fmaxf(ms, m[s]);
    }
    float lsum = 0.0f;
    #pragma unroll
    for (int s = 0; s < NSPLIT; s++) {
        wgt[s] = __expf(m[s] - ms);
        lsum += wgt[s] * g_l[s * NR + row];
    }
    float inv = 1.0f / lsum;

    size_t off = (size_t)row * DK + c4;
    float4 o = { 0.f, 0.f, 0.f, 0.f };
    #pragma unroll
    for (int s = 0; s < NSPLIT; s++) {
        float4 p = *(const float4*)&g_op[s][off];
        o.x += wgt[s] * p.x;  o.y += wgt[s] * p.y;
        o.z += wgt[s] * p.z;  o.w += wgt[s] * p.w;
    }
    o.x *= inv; o.y *= inv; o.z *= inv; o.w *= inv;
    *(float4*)&g_att[off] = o;
}

// ---------------------------------------------------------------------------
extern "C" void kernel_launch(void* const* d_in, const int* in_sizes, int n_in,
                              void* d_out, int out_size)
{
    const float* q    = (const float*)d_in[0];
    const float* k    = (const float*)d_in[1];
    const float* v    = (const float*)d_in[2];
    const int*   mask = (const int*)  d_in[3];
    const float* Wq   = (const float*)d_in[4];
    const float* bq   = (const float*)d_in[5];
    const float* Wk   = (const float*)d_in[6];
    const float* bk   = (const float*)d_in[7];
    const float* Wv   = (const float*)d_in[8];
    const float* bv   = (const float*)d_in[9];
    const float* Wo   = (const float*)d_in[10];
    const float* bo   = (const float*)d_in[11];
    float* out = (float*)d_out;

    cudaFuncSetAttribute(qkv_mma_kernel,
                         cudaFuncAttributeMaxDynamicSharedMemorySize, QKV_SMEM);

    const int M = BB * SS;  // 16384

    qkv_mma_kernel<<<dim3(M / 64, 3), 128, QKV_SMEM>>>(q, k, v,
                                                       Wq, bq, Wk, bk, Wv, bv);

    attn_mma_kernel<<<dim3(SS / 64, BB, NSPLIT), 128>>>(mask);
    attn_combine_kernel<<<(NR * 16) / 128, 128>>>();

    outproj_mma_kernel<<<dim3(M / 64, DM / 256), 128>>>(Wo, bo, out);
}

// round 12
// speedup vs baseline: 3.1252x; 1.1535x over previous
#include <cuda_runtime.h>
#include <cuda_fp16.h>
#include <cstdint>

#define BB 4
#define SS 4096
#define DM 1024
#define DK 64
#define NSPLIT 8
#define SPLITLEN (SS / NSPLIT)   // 512 keys per split
#define NR (BB * SS)             // 16384 rows

// Scratch (device globals per allocation-guard rules)
__device__ __half g_qh[BB * SS * DK];          // fp16 Q  [token][d]
__device__ __half g_kh[BB * SS * DK];          // fp16 K  [token][d]
__device__ __half g_vt[BB * DK * SS];          // fp16 V^T [b][dv][token]
__device__ float  g_att[BB * SS * DK];
__device__ float  g_op[NSPLIT][BB * SS * DK];  // unnormalized partial O
__device__ float  g_m[NSPLIT * NR];
__device__ float  g_l[NSPLIT * NR];

// ---------------------------------------------------------------------------
// helpers
// ---------------------------------------------------------------------------
__device__ __forceinline__ uint32_t f2tf(float f) {
    uint32_t u;
    asm("cvt.rna.tf32.f32 %0, %1;" : "=r"(u) : "f"(f));
    return u;
}
// pack two fp32 -> f16x2  (lo = first arg, hi = second arg)
__device__ __forceinline__ uint32_t pack_h2(float lo, float hi) {
    uint32_t r;
    asm("cvt.rn.f16x2.f32 %0, %1, %2;" : "=r"(r) : "f"(hi), "f"(lo));
    return r;
}

__device__ __forceinline__ void mma_tf32(float* d, const uint32_t* a,
                                         uint32_t b0, uint32_t b1) {
    asm volatile(
        "mma.sync.aligned.m16n8k8.row.col.f32.tf32.tf32.f32 "
        "{%0,%1,%2,%3}, {%4,%5,%6,%7}, {%8,%9}, {%0,%1,%2,%3};\n"
        : "+f"(d[0]), "+f"(d[1]), "+f"(d[2]), "+f"(d[3])
        : "r"(a[0]), "r"(a[1]), "r"(a[2]), "r"(a[3]), "r"(b0), "r"(b1));
}

__device__ __forceinline__ void mma_f16(float* d, const uint32_t* a,
                                        uint32_t b0, uint32_t b1) {
    asm volatile(
        "mma.sync.aligned.m16n8k16.row.col.f32.f16.f16.f32 "
        "{%0,%1,%2,%3}, {%4,%5,%6,%7}, {%8,%9}, {%0,%1,%2,%3};\n"
        : "+f"(d[0]), "+f"(d[1]), "+f"(d[2]), "+f"(d[3])
        : "r"(a[0]), "r"(a[1]), "r"(a[2]), "r"(a[3]), "r"(b0), "r"(b1));
}

// ldmatrix x4: 4 8x8 b16 tiles; thread lane supplies row (lane&7) of tile (lane>>3)
__device__ __forceinline__ void ldsm4(uint32_t* r, const void* p) {
    uint32_t a = (uint32_t)__cvta_generic_to_shared(p);
    asm volatile("ldmatrix.sync.aligned.m8n8.x4.shared.b16 {%0,%1,%2,%3}, [%4];"
                 : "=r"(r[0]), "=r"(r[1]), "=r"(r[2]), "=r"(r[3]) : "r"(a));
}

__device__ __forceinline__ void cp16(void* s, const void* g) {
    uint32_t sa = (uint32_t)__cvta_generic_to_shared(s);
    asm volatile("cp.async.cg.shared.global [%0], [%1], 16;" :: "r"(sa), "l"(g));
}
__device__ __forceinline__ void cp_commit() {
    asm volatile("cp.async.commit_group;");
}

// ---------------------------------------------------------------------------
// QKV projection, fp16 mma (m16n8k16) + ldmatrix B-frags.
// X: cp.async double-buffered fp32 (stride 72 words, conflict-free pairs);
// W: staged fp16 [n][d] stride 72 halves.  Epilogue writes fp16 Q/K and V^T.
// ---------------------------------------------------------------------------
#define XSTRW 72                                   // X buffer stride (words)
#define WSTRH 72                                   // W tile stride (halves)
#define QKV_XBUF (64 * XSTRW)                      // words per X buffer
#define QKV_SMEM (2 * QKV_XBUF * 4 + 64 * WSTRH * 2)   // 46080 bytes

__global__ __launch_bounds__(128, 4) void qkv_mma_kernel(
    const float* __restrict__ q, const float* __restrict__ k,
    const float* __restrict__ v,
    const float* __restrict__ Wq, const float* __restrict__ bq,
    const float* __restrict__ Wk, const float* __restrict__ bk,
    const float* __restrict__ Wv, const float* __restrict__ bv)
{
    extern __shared__ uint32_t sq[];
    float*  Xb0 = reinterpret_cast<float*>(sq);
    float*  Xb1 = Xb0 + QKV_XBUF;
    __half* Wh  = reinterpret_cast<__half*>(sq + 2 * QKV_XBUF);

    const int which = blockIdx.y;
    const float* X    = (which == 0) ? q  : (which == 1) ? k  : v;
    const float* W    = (which == 0) ? Wq : (which == 1) ? Wk : Wv;
    const float* bias = (which == 0) ? bq : (which == 1) ? bk : bv;

    const int m0   = blockIdx.x * 64;
    const int t    = threadIdx.x;
    const int w    = t >> 5;
    const int lane = t & 31;
    const int gi   = lane >> 2;
    const int gc   = lane & 3;

    const int srow = t >> 4;            // 0..7 staging row base
    const int sc4  = (t & 15) << 2;     // staging col

    #pragma unroll
    for (int j = 0; j < 8; j++) {
        int row = srow + j * 8;
        cp16(&Xb0[row * XSTRW + sc4], &X[(size_t)(m0 + row) * DM + sc4]);
    }
    cp_commit();

    float acc[8][4] = {};
    const int ra = 16 * w + gi, rb = ra + 8;

    // ldmatrix base offsets (halves) for B tiles
    const int lrow = lane & 7;          // row within 8x8 tile
    const int ldk  = 8 * (lane >> 3);   // d offset of this thread's tile

    for (int kc0 = 0; kc0 < 16; kc0++) {
        float* Xs = (kc0 & 1) ? Xb1 : Xb0;
        const int k0 = kc0 * 64;

        // stage W chunk as fp16 [n][d] (LDG fp32 + pack + STS.64)
        #pragma unroll
        for (int j = 0; j < 8; j++) {
            int f   = t + j * 128;
            int row = f >> 4;
            int c4  = (f & 15) << 2;
            float4 wv = *(const float4*)&W[(size_t)row * DM + k0 + c4];
            uint2  wu = { pack_h2(wv.x, wv.y), pack_h2(wv.z, wv.w) };
            *reinterpret_cast<uint2*>(&Wh[row * WSTRH + c4]) = wu;
        }

        if (kc0 + 1 < 16) {
            float* Xn = (kc0 & 1) ? Xb0 : Xb1;
            int k0n = k0 + 64;
            #pragma unroll
            for (int j = 0; j < 8; j++) {
                int row = srow + j * 8;
                cp16(&Xn[row * XSTRW + sc4], &X[(size_t)(m0 + row) * DM + k0n + sc4]);
            }
        }
        cp_commit();

        asm volatile("cp.async.wait_group 1;");
        __syncthreads();

        // A fragments: pack fp32 pairs from Xs (conflict-free, stride 72)
        uint32_t aq[4][4];
        #pragma unroll
        for (int kc = 0; kc < 4; kc++) {
            int d = 16 * kc + 2 * gc;
            float2 xa = *(const float2*)&Xs[ra * XSTRW + d    ];
            float2 xb = *(const float2*)&Xs[rb * XSTRW + d    ];
            float2 xc = *(const float2*)&Xs[ra * XSTRW + d + 8];
            float2 xd = *(const float2*)&Xs[rb * XSTRW + d + 8];
            aq[kc][0] = pack_h2(xa.x, xa.y);
            aq[kc][1] = pack_h2(xb.x, xb.y);
            aq[kc][2] = pack_h2(xc.x, xc.y);
            aq[kc][3] = pack_h2(xd.x, xd.y);
        }

        #pragma unroll
        for (int nt = 0; nt < 8; nt++) {
            const __half* bp = Wh + (8 * nt + lrow) * WSTRH + ldk;
            uint32_t bfr[8];
            ldsm4(bfr    , bp     );   // tiles d = 0,8,16,24  (kc 0,1)
            ldsm4(bfr + 4, bp + 32);   // tiles d = 32..56     (kc 2,3)
            mma_f16(acc[nt], aq[0], bfr[0], bfr[1]);
            mma_f16(acc[nt], aq[1], bfr[2], bfr[3]);
            mma_f16(acc[nt], aq[2], bfr[4], bfr[5]);
            mma_f16(acc[nt], aq[3], bfr[6], bfr[7]);
        }
        __syncthreads();
    }

    if (which != 2) {
        __half* outh = (which == 0) ? g_qh : g_kh;
        #pragma unroll
        for (int nt = 0; nt < 8; nt++) {
            int n = 8 * nt + 2 * gc;
            float2 b2 = *(const float2*)&bias[n];
            uint32_t ha = pack_h2(acc[nt][0] + b2.x, acc[nt][1] + b2.y);
            *(uint32_t*)&outh[(size_t)(m0 + ra) * DK + n] = ha;
            uint32_t hb = pack_h2(acc[nt][2] + b2.x, acc[nt][3] + b2.y);
            *(uint32_t*)&outh[(size_t)(m0 + rb) * DK + n] = hb;
        }
    } else {
        int bidx = (m0 + ra) >> 12;
        int sa   = (m0 + ra) & (SS - 1);
        int sb   = (m0 + rb) & (SS - 1);
        __half* vt = g_vt + (size_t)bidx * DK * SS;
        #pragma unroll
        for (int nt = 0; nt < 8; nt++) {
            int n = 8 * nt + 2 * gc;
            float2 b2 = *(const float2*)&bias[n];
            vt[(size_t)(n    ) * SS + sa] = __float2half_rn(acc[nt][0] + b2.x);
            vt[(size_t)(n + 1) * SS + sa] = __float2half_rn(acc[nt][1] + b2.y);
            vt[(size_t)(n    ) * SS + sb] = __float2half_rn(acc[nt][2] + b2.x);
            vt[(size_t)(n + 1) * SS + sb] = __float2half_rn(acc[nt][3] + b2.y);
        }
    }
}

// ---------------------------------------------------------------------------
// Output projection via tf32 mma (unchanged from R10).
// ---------------------------------------------------------------------------
__global__ __launch_bounds__(128, 4) void outproj_mma_kernel(const float* __restrict__ Wo,
                                                             const float* __restrict__ bo,
                                                             float* __restrict__ out)
{
    __shared__ uint32_t As[64 * 68];
    __shared__ uint32_t Ws[64 * 80];

    const int m0   = blockIdx.x * 64;
    const int n00  = blockIdx.y * 256;
    const int t    = threadIdx.x;
    const int w    = t >> 5;
    const int lane = t & 31;
    const int gi   = lane >> 2;
    const int gc   = lane & 3;

    #pragma unroll
    for (int j = 0; j < 8; j++) {
        int f   = t + j * 128;
        int row = f >> 4;
        int c4  = (f & 15) << 2;
        float4 av = *(const float4*)&g_att[(size_t)(m0 + row) * DK + c4];
        uint4  au = { f2tf(av.x), f2tf(av.y), f2tf(av.z), f2tf(av.w) };
        *reinterpret_cast<uint4*>(&As[row * 68 + c4]) = au;
    }

    const int ra = 16 * w + gi, rb = ra + 8;
    uint32_t aq[8][4];
    bool aq_done = false;

    for (int ny = 0; ny < 4; ny++) {
        const int n0 = n00 + 64 * ny;

        #pragma unroll
        for (int j = 0; j < 8; j++) {
            int f   = t + j * 128;
            int row = f >> 4;
            int c4  = (f & 15) << 2;
            float4 wv = *(const float4*)&Wo[(size_t)(n0 + row) * DK + c4];
            uint4  wu = { f2tf(wv.x), f2tf(wv.y), f2tf(wv.z), f2tf(wv.w) };
            *reinterpret_cast<uint4*>(&Ws[row * 80 + c4]) = wu;
        }
        __syncthreads();

        if (!aq_done) {
            aq_done = true;
            #pragma unroll
            for (int kc = 0; kc < 4; kc++) {
                int d = 16 * kc + 4 * gc;
                aq[2*kc  ][0] = As[ra * 68 + d    ];
                aq[2*kc  ][1] = As[rb * 68 + d    ];
                aq[2*kc  ][2] = As[ra * 68 + d + 1];
                aq[2*kc  ][3] = As[rb * 68 + d + 1];
                aq[2*kc+1][0] = As[ra * 68 + d + 2];
                aq[2*kc+1][1] = As[rb * 68 + d + 2];
                aq[2*kc+1][2] = As[ra * 68 + d + 3];
                aq[2*kc+1][3] = As[rb * 68 + d + 3];
            }
        }

        float acc[8][4] = {};
        #pragma unroll
        for (int nt = 0; nt < 8; nt++) {
            const uint32_t* kp = Ws + (8 * nt + gi) * 80 + 4 * gc;
            #pragma unroll
            for (int kc = 0; kc < 4; kc++) {
                uint4 bb = *reinterpret_cast<const uint4*>(kp + 16 * kc);
                mma_tf32(acc[nt], aq[2*kc    ], bb.x, bb.y);
                mma_tf32(acc[nt], aq[2*kc + 1], bb.z, bb.w);
            }
        }

        #pragma unroll
        for (int nt = 0; nt < 8; nt++) {
            int n = n0 + 8 * nt + 2 * gc;
            float2 b2 = *(const float2*)&bo[n];
            float2 oa = { acc[nt][0] + b2.x, acc[nt][1] + b2.y };
            *(float2*)&out[(size_t)(m0 + ra) * DM + n] = oa;
            float2 ob = { acc[nt][2] + b2.x, acc[nt][3] + b2.y };
            *(float2*)&out[(size_t)(m0 + rb) * DM + n] = ob;
        }
        __syncthreads();
    }
}

// ---------------------------------------------------------------------------
// Split-K flash attention, fp16 mma + ldmatrix B-frags.
// Grid (SS/64, BB, NSPLIT) = 2048 blocks, 128 threads.
// ---------------------------------------------------------------------------
#define HSTR 72   // halfword stride for K / Vt / Q smem tiles

__global__ __launch_bounds__(128, 4) void attn_mma_kernel(const int* __restrict__ mask)
{
    __shared__ __half sh[64 * HSTR * 2];   // 18432 B
    __half* Ks  = sh;                 // [64 keys][HSTR]
    __half* Vts = sh + 64 * HSTR;     // [64 dv][HSTR]
    __half* Qs  = sh;                 // staging overlay [64 rows][HSTR]

    const int b     = blockIdx.y;
    const int q0    = blockIdx.x * 64;
    const int split = blockIdx.z;
    const int t     = threadIdx.x;
    const int w     = t >> 5;
    const int lane  = t & 31;
    const int gi    = lane >> 2;
    const int gc    = lane & 3;
    const float scale = 0.125f;

    const int ra = 16 * w + gi, rb = ra + 8;
    const int lrow = lane & 7;          // ldmatrix row within tile
    const int ldk  = 8 * (lane >> 3);   // ldmatrix tile d-offset

    // ---- stage Q (fp16) and extract A fragments ----
    const __half* qh = g_qh + ((size_t)b * SS + q0) * DK;
    #pragma unroll
    for (int j = 0; j < 4; j++) {
        int f   = t + j * 128;        // 0..511
        int row = f >> 3;
        int dg  = (f & 7) << 3;
        *reinterpret_cast<uint4*>(&Qs[row * HSTR + dg]) =
            *reinterpret_cast<const uint4*>(&qh[row * DK + dg]);
    }
    __syncthreads();

    uint32_t aq[4][4];
    #pragma unroll
    for (int kc = 0; kc < 4; kc++) {
        int d = 16 * kc + 2 * gc;
        aq[kc][0] = *(const uint32_t*)&Qs[ra * HSTR + d    ];
        aq[kc][1] = *(const uint32_t*)&Qs[rb * HSTR + d    ];
        aq[kc][2] = *(const uint32_t*)&Qs[ra * HSTR + d + 8];
        aq[kc][3] = *(const uint32_t*)&Qs[rb * HSTR + d + 8];
    }
    __syncthreads();

    float oacc[8][4] = {};
    float m_a = -1e30f, m_b = -1e30f, l_a = 0.0f, l_b = 0.0f;

    const int qa = q0 + ra;
    const int qb = q0 + rb;

    const __half* khb = g_kh + (size_t)b * SS * DK;
    const __half* vtb = g_vt + (size_t)b * DK * SS;
    const int2* mrow_a = (const int2*)(mask + (size_t)qa * SS);
    const int2* mrow_b = (const int2*)(mask + (size_t)qb * SS);

    const int kbeg = split * SPLITLEN;
    const int kend = kbeg + SPLITLEN;

    for (int kt = kbeg; kt < kend; kt += 64) {
        // ---- stage K [key][d] and V^T [dv][key] ----
        #pragma unroll
        for (int j = 0; j < 4; j++) {
            int f   = t + j * 128;
            int r   = f >> 3;
            int dg  = (f & 7) << 3;
            *reinterpret_cast<uint4*>(&Ks[r * HSTR + dg]) =
                *reinterpret_cast<const uint4*>(&khb[(size_t)(kt + r) * DK + dg]);
            *reinterpret_cast<uint4*>(&Vts[r * HSTR + dg]) =
                *reinterpret_cast<const uint4*>(&vtb[(size_t)r * SS + kt + dg]);
        }
        __syncthreads();

        // ---- GEMM1: S = Q . K^T  (ldmatrix B-frags) ----
        float sacc[8][4];
        #pragma unroll
        for (int nt = 0; nt < 8; nt++) {
            sacc[nt][0] = 0.f; sacc[nt][1] = 0.f;
            sacc[nt][2] = 0.f; sacc[nt][3] = 0.f;
        }
        #pragma unroll
        for (int nt = 0; nt < 8; nt++) {
            const __half* bp = Ks + (8 * nt + lrow) * HSTR + ldk;
            uint32_t bfr[8];
            ldsm4(bfr    , bp     );
            ldsm4(bfr + 4, bp + 32);
            mma_f16(sacc[nt], aq[0], bfr[0], bfr[1]);
            mma_f16(sacc[nt], aq[1], bfr[2], bfr[3]);
            mma_f16(sacc[nt], aq[2], bfr[4], bfr[5]);
            mma_f16(sacc[nt], aq[3], bfr[6], bfr[7]);
        }

        // ---- scale + mask ----
        const int mbase = (kt >> 1) + gc;
        #pragma unroll
        for (int nt = 0; nt < 8; nt++) {
            int2 ma = mrow_a[mbase + 4 * nt];
            int2 mb = mrow_b[mbase + 4 * nt];
            sacc[nt][0] = ma.x ? sacc[nt][0] * scale : -1e9f;
            sacc[nt][1] = ma.y ? sacc[nt][1] * scale : -1e9f;
            sacc[nt][2] = mb.x ? sacc[nt][2] * scale : -1e9f;
            sacc[nt][3] = mb.y ? sacc[nt][3] * scale : -1e9f;
        }

        // ---- online softmax ----
        float mxa = -1e30f, mxb = -1e30f;
        #pragma unroll
        for (int nt = 0; nt < 8; nt++) {
            mxa = fmaxf(mxa, fmaxf(sacc[nt][0], sacc[nt][1]));
            mxb = fmaxf(mxb, fmaxf(sacc[nt][2], sacc[nt][3]));
        }
        mxa = fmaxf(mxa, __shfl_xor_sync(0xffffffffu, mxa, 1));
        mxa = fmaxf(mxa, __shfl_xor_sync(0xffffffffu, mxa, 2));
        mxb = fmaxf(mxb, __shfl_xor_sync(0xffffffffu, mxb, 1));
        mxb = fmaxf(mxb, __shfl_xor_sync(0xffffffffu, mxb, 2));

        float mna = fmaxf(m_a, mxa);
        float mnb = fmaxf(m_b, mxb);
        float ca = __expf(m_a - mna);  m_a = mna;
        float cb = __expf(m_b - mnb);  m_b = mnb;

        // ---- P = exp(S-m), packed into f16 A-fragments ----
        uint32_t pa[4][4];
        float sla = 0.0f, slb = 0.0f;
        #pragma unroll
        for (int nt = 0; nt < 8; nt++) {
            float p0 = __expf(sacc[nt][0] - m_a);
            float p1 = __expf(sacc[nt][1] - m_a);
            float p2 = __expf(sacc[nt][2] - m_b);
            float p3 = __expf(sacc[nt][3] - m_b);
            sla += p0 + p1;
            slb += p2 + p3;
            int g = nt >> 1;
            int h = (nt & 1) << 1;
            pa[g][h    ] = pack_h2(p0, p1);
            pa[g][h + 1] = pack_h2(p2, p3);
        }
        sla += __shfl_xor_sync(0xffffffffu, sla, 1);
        sla += __shfl_xor_sync(0xffffffffu, sla, 2);
        slb += __shfl_xor_sync(0xffffffffu, slb, 1);
        slb += __shfl_xor_sync(0xffffffffu, slb, 2);
        l_a = l_a * ca + sla;
        l_b = l_b * cb + slb;

        #pragma unroll
        for (int nt = 0; nt < 8; nt++) {
            oacc[nt][0] *= ca; oacc[nt][1] *= ca;
            oacc[nt][2] *= cb; oacc[nt][3] *= cb;
        }

        // ---- GEMM2: O += P . V  (ldmatrix B-frags from V^T tile) ----
        #pragma unroll
        for (int nt = 0; nt < 8; nt++) {
            const __half* vp = Vts + (8 * nt + lrow) * HSTR + ldk;
            uint32_t bfr[8];
            ldsm4(bfr    , vp     );
            ldsm4(bfr + 4, vp + 32);
            mma_f16(oacc[nt], pa[0], bfr[0], bfr[1]);
            mma_f16(oacc[nt], pa[1], bfr[2], bfr[3]);
            mma_f16(oacc[nt], pa[2], bfr[4], bfr[5]);
            mma_f16(oacc[nt], pa[3], bfr[6], bfr[7]);
        }
        __syncthreads();
    }

    // ---- write unnormalized partial O + (m, l) ----
    const size_t rowa = (size_t)b * SS + qa;
    const size_t rowb = (size_t)b * SS + qb;
    float* op = g_op[split];
    #pragma unroll
    for (int nt = 0; nt < 8; nt++) {
        float2 oa = { oacc[nt][0], oacc[nt][1] };
        *(float2*)&op[rowa * DK + 8 * nt + 2 * gc] = oa;
        float2 ob = { oacc[nt][2], oacc[nt][3] };
        *(float2*)&op[rowb * DK + 8 * nt + 2 * gc] = ob;
    }
    if (gc == 0) {
        g_m[split * NR + rowa] = m_a;
        g_l[split * NR + rowa] = l_a;
        g_m[split * NR + rowb] = m_b;
        g_l[split * NR + rowb] = l_b;
    }
}

// ---------------------------------------------------------------------------
// Combine the NSPLIT partials.
// ---------------------------------------------------------------------------
__global__ __launch_bounds__(128) void attn_combine_kernel()
{
    int idx = blockIdx.x * 128 + threadIdx.x;
    int row = idx >> 4;
    int c4  = (idx & 15) << 2;

    float m[NSPLIT], wgt[NSPLIT];
    float ms = -1e30f;
    #pragma unroll
    for (int s = 0; s < NSPLIT; s++) {
        m[s] = g_m[s * NR + row];
        ms = fmaxf(ms, m[s]);
    }
    float lsum = 0.0f;
    #pragma unroll
    for (int s = 0; s < NSPLIT; s++) {
        wgt[s] = __expf(m[s] - ms);
        lsum += wgt[s] * g_l[s * NR + row];
    }
    float inv = 1.0f / lsum;

    size_t off = (size_t)row * DK + c4;
    float4 o = { 0.f, 0.f, 0.f, 0.f };
    #pragma unroll
    for (int s = 0; s < NSPLIT; s++) {
        float4 p = *(const float4*)&g_op[s][off];
        o.x += wgt[s] * p.x;  o.y += wgt[s] * p.y;
        o.z += wgt[s] * p.z;  o.w += wgt[s] * p.w;
    }
    o.x *= inv; o.y *= inv; o.z *= inv; o.w *= inv;
    *(float4*)&g_att[off] = o;
}

// ---------------------------------------------------------------------------
extern "C" void kernel_launch(void* const* d_in, const int* in_sizes, int n_in,
                              void* d_out, int out_size)
{
    const float* q    = (const float*)d_in[0];
    const float* k    = (const float*)d_in[1];
    const float* v    = (const float*)d_in[2];
    const int*   mask = (const int*)  d_in[3];
    const float* Wq   = (const float*)d_in[4];
    const float* bq   = (const float*)d_in[5];
    const float* Wk   = (const float*)d_in[6];
    const float* bk   = (const float*)d_in[7];
    const float* Wv   = (const float*)d_in[8];
    const float* bv   = (const float*)d_in[9];
    const float* Wo   = (const float*)d_in[10];
    const float* bo   = (const float*)d_in[11];
    float* out = (float*)d_out;

    cudaFuncSetAttribute(qkv_mma_kernel,
                         cudaFuncAttributeMaxDynamicSharedMemorySize, QKV_SMEM);

    const int M = BB * SS;  // 16384

    qkv_mma_kernel<<<dim3(M / 64, 3), 128, QKV_SMEM>>>(q, k, v,
                                                       Wq, bq, Wk, bk, Wv, bv);

    attn_mma_kernel<<<dim3(SS / 64, BB, NSPLIT), 128>>>(mask);
    attn_combine_kernel<<<(NR * 16) / 128, 128>>>();

    outproj_mma_kernel<<<dim3(M / 64, DM / 256), 128>>>(Wo, bo, out);
}

// round 13
// speedup vs baseline: 3.2098x; 1.0271x over previous
#include <cuda_runtime.h>
#include <cuda_fp16.h>
#include <cstdint>

#define BB 4
#define SS 4096
#define DM 1024
#define DK 64
#define NSPLIT 8
#define SPLITLEN (SS / NSPLIT)   // 512 keys per split
#define NR (BB * SS)             // 16384 rows

// Scratch (device globals per allocation-guard rules)
__device__ __half g_qh[BB * SS * DK];          // fp16 Q  [token][d]
__device__ __half g_kh[BB * SS * DK];          // fp16 K  [token][d]
__device__ __half g_vt[BB * DK * SS];          // fp16 V^T [b][dv][token]
__device__ __half g_atth[BB * SS * DK];        // fp16 attention output
__device__ __half g_wh[3 * DK * DM];           // fp16 Wq|Wk|Wv  [n][d]
__device__ __half g_woh[DM * DK];              // fp16 Wo [n][v]
__device__ float  g_op[NSPLIT][BB * SS * DK];  // unnormalized partial O
__device__ float  g_m[NSPLIT * NR];
__device__ float  g_l[NSPLIT * NR];

// ---------------------------------------------------------------------------
// helpers
// ---------------------------------------------------------------------------
// pack two fp32 -> f16x2  (lo = first arg, hi = second arg)
__device__ __forceinline__ uint32_t pack_h2(float lo, float hi) {
    uint32_t r;
    asm("cvt.rn.f16x2.f32 %0, %1, %2;" : "=r"(r) : "f"(hi), "f"(lo));
    return r;
}

__device__ __forceinline__ void mma_f16(float* d, const uint32_t* a,
                                        uint32_t b0, uint32_t b1) {
    asm volatile(
        "mma.sync.aligned.m16n8k16.row.col.f32.f16.f16.f32 "
        "{%0,%1,%2,%3}, {%4,%5,%6,%7}, {%8,%9}, {%0,%1,%2,%3};\n"
        : "+f"(d[0]), "+f"(d[1]), "+f"(d[2]), "+f"(d[3])
        : "r"(a[0]), "r"(a[1]), "r"(a[2]), "r"(a[3]), "r"(b0), "r"(b1));
}

// ldmatrix x4: 4 8x8 b16 tiles; thread lane supplies row (lane&7) of tile (lane>>3)
__device__ __forceinline__ void ldsm4(uint32_t* r, const void* p) {
    uint32_t a = (uint32_t)__cvta_generic_to_shared(p);
    asm volatile("ldmatrix.sync.aligned.m8n8.x4.shared.b16 {%0,%1,%2,%3}, [%4];"
                 : "=r"(r[0]), "=r"(r[1]), "=r"(r[2]), "=r"(r[3]) : "r"(a));
}

__device__ __forceinline__ void cp16(void* s, const void* g) {
    uint32_t sa = (uint32_t)__cvta_generic_to_shared(s);
    asm volatile("cp.async.cg.shared.global [%0], [%1], 16;" :: "r"(sa), "l"(g));
}
__device__ __forceinline__ void cp_commit() {
    asm volatile("cp.async.commit_group;");
}

// ---------------------------------------------------------------------------
// Prep: one-shot fp32 -> fp16 conversion of the weight matrices.
// blockIdx.y: 0=Wq, 1=Wk, 2=Wv, 3=Wo.  65536 elements each, 4 per thread.
// ---------------------------------------------------------------------------
__global__ __launch_bounds__(128) void prep_weights_kernel(
    const float* __restrict__ Wq, const float* __restrict__ Wk,
    const float* __restrict__ Wv, const float* __restrict__ Wo)
{
    const int which = blockIdx.y;
    const float* src = (which == 0) ? Wq : (which == 1) ? Wk
                     : (which == 2) ? Wv : Wo;
    __half* dst = (which < 3) ? (g_wh + (size_t)which * DK * DM) : g_woh;

    int idx = (blockIdx.x * 128 + threadIdx.x) * 4;
    float4 v = *(const float4*)&src[idx];
    uint2 h = { pack_h2(v.x, v.y), pack_h2(v.z, v.w) };
    *(uint2*)&dst[idx] = h;
}

// ---------------------------------------------------------------------------
// QKV projection, fp16 mma + ldmatrix.  X: cp.async double-buffered fp32;
// W: fp16 from g_wh (straight copies).  Epilogue writes fp16 Q/K and V^T.
// ---------------------------------------------------------------------------
#define XSTRW 72                                   // X buffer stride (words)
#define WSTRH 72                                   // W tile stride (halves)
#define QKV_XBUF (64 * XSTRW)                      // words per X buffer
#define QKV_SMEM (2 * QKV_XBUF * 4 + 64 * WSTRH * 2)   // 46080 bytes

__global__ __launch_bounds__(128, 4) void qkv_mma_kernel(
    const float* __restrict__ q, const float* __restrict__ k,
    const float* __restrict__ v,
    const float* __restrict__ bq, const float* __restrict__ bk,
    const float* __restrict__ bv)
{
    extern __shared__ uint32_t sq[];
    float*  Xb0 = reinterpret_cast<float*>(sq);
    float*  Xb1 = Xb0 + QKV_XBUF;
    __half* Wh  = reinterpret_cast<__half*>(sq + 2 * QKV_XBUF);

    const int which = blockIdx.y;
    const float* X    = (which == 0) ? q  : (which == 1) ? k  : v;
    const float* bias = (which == 0) ? bq : (which == 1) ? bk : bv;
    const __half* Wsrc = g_wh + (size_t)which * DK * DM;

    const int m0   = blockIdx.x * 64;
    const int t    = threadIdx.x;
    const int w    = t >> 5;
    const int lane = t & 31;
    const int gi   = lane >> 2;
    const int gc   = lane & 3;

    const int srow = t >> 4;            // 0..7 staging row base (X, fp32)
    const int sc4  = (t & 15) << 2;

    const int hrow = t >> 3;            // 0..15 staging row base (W, fp16)
    const int hc8  = (t & 7) << 3;

    #pragma unroll
    for (int j = 0; j < 8; j++) {
        int row = srow + j * 8;
        cp16(&Xb0[row * XSTRW + sc4], &X[(size_t)(m0 + row) * DM + sc4]);
    }
    cp_commit();

    float acc[8][4] = {};
    const int ra = 16 * w + gi, rb = ra + 8;

    const int lrow = lane & 7;          // ldmatrix row within tile
    const int ldk  = 8 * (lane >> 3);   // ldmatrix tile d-offset

    for (int kc0 = 0; kc0 < 16; kc0++) {
        float* Xs = (kc0 & 1) ? Xb1 : Xb0;
        const int k0 = kc0 * 64;

        // stage W chunk (fp16 straight copy, 4 LDG.128 + 4 STS.128)
        #pragma unroll
        for (int j = 0; j < 4; j++) {
            int row = hrow + j * 16;
            *reinterpret_cast<uint4*>(&Wh[row * WSTRH + hc8]) =
                *reinterpret_cast<const uint4*>(&Wsrc[(size_t)row * DM + k0 + hc8]);
        }

        if (kc0 + 1 < 16) {
            float* Xn = (kc0 & 1) ? Xb0 : Xb1;
            int k0n = k0 + 64;
            #pragma unroll
            for (int j = 0; j < 8; j++) {
                int row = srow + j * 8;
                cp16(&Xn[row * XSTRW + sc4], &X[(size_t)(m0 + row) * DM + k0n + sc4]);
            }
        }
        cp_commit();

        asm volatile("cp.async.wait_group 1;");
        __syncthreads();

        // A fragments: pack fp32 pairs from Xs
        uint32_t aq[4][4];
        #pragma unroll
        for (int kc = 0; kc < 4; kc++) {
            int d = 16 * kc + 2 * gc;
            float2 xa = *(const float2*)&Xs[ra * XSTRW + d    ];
            float2 xb = *(const float2*)&Xs[rb * XSTRW + d    ];
            float2 xc = *(const float2*)&Xs[ra * XSTRW + d + 8];
            float2 xd = *(const float2*)&Xs[rb * XSTRW + d + 8];
            aq[kc][0] = pack_h2(xa.x, xa.y);
            aq[kc][1] = pack_h2(xb.x, xb.y);
            aq[kc][2] = pack_h2(xc.x, xc.y);
            aq[kc][3] = pack_h2(xd.x, xd.y);
        }

        #pragma unroll
        for (int nt = 0; nt < 8; nt++) {
            const __half* bp = Wh + (8 * nt + lrow) * WSTRH + ldk;
            uint32_t bfr[8];
            ldsm4(bfr    , bp     );
            ldsm4(bfr + 4, bp + 32);
            mma_f16(acc[nt], aq[0], bfr[0], bfr[1]);
            mma_f16(acc[nt], aq[1], bfr[2], bfr[3]);
            mma_f16(acc[nt], aq[2], bfr[4], bfr[5]);
            mma_f16(acc[nt], aq[3], bfr[6], bfr[7]);
        }
        __syncthreads();
    }

    if (which != 2) {
        __half* outh = (which == 0) ? g_qh : g_kh;
        #pragma unroll
        for (int nt = 0; nt < 8; nt++) {
            int n = 8 * nt + 2 * gc;
            float2 b2 = *(const float2*)&bias[n];
            uint32_t ha = pack_h2(acc[nt][0] + b2.x, acc[nt][1] + b2.y);
            *(uint32_t*)&outh[(size_t)(m0 + ra) * DK + n] = ha;
            uint32_t hb = pack_h2(acc[nt][2] + b2.x, acc[nt][3] + b2.y);
            *(uint32_t*)&outh[(size_t)(m0 + rb) * DK + n] = hb;
        }
    } else {
        int bidx = (m0 + ra) >> 12;
        int sa   = (m0 + ra) & (SS - 1);
        int sb   = (m0 + rb) & (SS - 1);
        __half* vt = g_vt + (size_t)bidx * DK * SS;
        #pragma unroll
        for (int nt = 0; nt < 8; nt++) {
            int n = 8 * nt + 2 * gc;
            float2 b2 = *(const float2*)&bias[n];
            vt[(size_t)(n    ) * SS + sa] = __float2half_rn(acc[nt][0] + b2.x);
            vt[(size_t)(n + 1) * SS + sa] = __float2half_rn(acc[nt][1] + b2.y);
            vt[(size_t)(n    ) * SS + sb] = __float2half_rn(acc[nt][2] + b2.x);
            vt[(size_t)(n + 1) * SS + sb] = __float2half_rn(acc[nt][3] + b2.y);
        }
    }
}

// ---------------------------------------------------------------------------
// Output projection, fp16 mma + ldmatrix.  A = g_atth (fp16), W = g_woh.
// Block: 64 rows x 256 cols (4 n-tiles), grid (256, 4).
// ---------------------------------------------------------------------------
__global__ __launch_bounds__(128, 4) void outproj_mma_kernel(const float* __restrict__ bo,
                                                             float* __restrict__ out)
{
    __shared__ __half sh[64 * WSTRH * 2];   // 18432 B
    __half* As = sh;
    __half* Ws = sh + 64 * WSTRH;

    const int m0   = blockIdx.x * 64;
    const int n00  = blockIdx.y * 256;
    const int t    = threadIdx.x;
    const int w    = t >> 5;
    const int lane = t & 31;
    const int gi   = lane >> 2;
    const int gc   = lane & 3;

    const int hrow = t >> 3;
    const int hc8  = (t & 7) << 3;
    const int lrow = lane & 7;
    const int ldk  = 8 * (lane >> 3);

    // stage A tile (fp16) once
    #pragma unroll
    for (int j = 0; j < 4; j++) {
        int row = hrow + j * 16;
        *reinterpret_cast<uint4*>(&As[row * WSTRH + hc8]) =
            *reinterpret_cast<const uint4*>(&g_atth[(size_t)(m0 + row) * DK + hc8]);
    }

    const int ra = 16 * w + gi, rb = ra + 8;
    uint32_t aq[4][4];
    bool aq_done = false;

    for (int ny = 0; ny < 4; ny++) {
        const int n0 = n00 + 64 * ny;

        #pragma unroll
        for (int j = 0; j < 4; j++) {
            int row = hrow + j * 16;
            *reinterpret_cast<uint4*>(&Ws[row * WSTRH + hc8]) =
                *reinterpret_cast<const uint4*>(&g_woh[(size_t)(n0 + row) * DK + hc8]);
        }
        __syncthreads();

        if (!aq_done) {
            aq_done = true;
            #pragma unroll
            for (int kc = 0; kc < 4; kc++) {
                int d = 16 * kc + 2 * gc;
                aq[kc][0] = *(const uint32_t*)&As[ra * WSTRH + d    ];
                aq[kc][1] = *(const uint32_t*)&As[rb * WSTRH + d    ];
                aq[kc][2] = *(const uint32_t*)&As[ra * WSTRH + d + 8];
                aq[kc][3] = *(const uint32_t*)&As[rb * WSTRH + d + 8];
            }
        }

        float acc[8][4] = {};
        #pragma unroll
        for (int nt = 0; nt < 8; nt++) {
            const __half* bp = Ws + (8 * nt + lrow) * WSTRH + ldk;
            uint32_t bfr[8];
            ldsm4(bfr    , bp     );
            ldsm4(bfr + 4, bp + 32);
            mma_f16(acc[nt], aq[0], bfr[0], bfr[1]);
            mma_f16(acc[nt], aq[1], bfr[2], bfr[3]);
            mma_f16(acc[nt], aq[2], bfr[4], bfr[5]);
            mma_f16(acc[nt], aq[3], bfr[6], bfr[7]);
        }

        #pragma unroll
        for (int nt = 0; nt < 8; nt++) {
            int n = n0 + 8 * nt + 2 * gc;
            float2 b2 = *(const float2*)&bo[n];
            float2 oa = { acc[nt][0] + b2.x, acc[nt][1] + b2.y };
            *(float2*)&out[(size_t)(m0 + ra) * DM + n] = oa;
            float2 ob = { acc[nt][2] + b2.x, acc[nt][3] + b2.y };
            *(float2*)&out[(size_t)(m0 + rb) * DM + n] = ob;
        }
        __syncthreads();
    }
}

// ---------------------------------------------------------------------------
// Split-K flash attention, fp16 mma + ldmatrix (unchanged from R11).
// ---------------------------------------------------------------------------
#define HSTR 72

__global__ __launch_bounds__(128, 4) void attn_mma_kernel(const int* __restrict__ mask)
{
    __shared__ __half sh[64 * HSTR * 2];   // 18432 B
    __half* Ks  = sh;
    __half* Vts = sh + 64 * HSTR;
    __half* Qs  = sh;

    const int b     = blockIdx.y;
    const int q0    = blockIdx.x * 64;
    const int split = blockIdx.z;
    const int t     = threadIdx.x;
    const int w     = t >> 5;
    const int lane  = t & 31;
    const int gi    = lane >> 2;
    const int gc    = lane & 3;
    const float scale = 0.125f;

    const int ra = 16 * w + gi, rb = ra + 8;
    const int lrow = lane & 7;
    const int ldk  = 8 * (lane >> 3);

    const __half* qh = g_qh + ((size_t)b * SS + q0) * DK;
    #pragma unroll
    for (int j = 0; j < 4; j++) {
        int f   = t + j * 128;
        int row = f >> 3;
        int dg  = (f & 7) << 3;
        *reinterpret_cast<uint4*>(&Qs[row * HSTR + dg]) =
            *reinterpret_cast<const uint4*>(&qh[row * DK + dg]);
    }
    __syncthreads();

    uint32_t aq[4][4];
    #pragma unroll
    for (int kc = 0; kc < 4; kc++) {
        int d = 16 * kc + 2 * gc;
        aq[kc][0] = *(const uint32_t*)&Qs[ra * HSTR + d    ];
        aq[kc][1] = *(const uint32_t*)&Qs[rb * HSTR + d    ];
        aq[kc][2] = *(const uint32_t*)&Qs[ra * HSTR + d + 8];
        aq[kc][3] = *(const uint32_t*)&Qs[rb * HSTR + d + 8];
    }
    __syncthreads();

    float oacc[8][4] = {};
    float m_a = -1e30f, m_b = -1e30f, l_a = 0.0f, l_b = 0.0f;

    const int qa = q0 + ra;
    const int qb = q0 + rb;

    const __half* khb = g_kh + (size_t)b * SS * DK;
    const __half* vtb = g_vt + (size_t)b * DK * SS;
    const int2* mrow_a = (const int2*)(mask + (size_t)qa * SS);
    const int2* mrow_b = (const int2*)(mask + (size_t)qb * SS);

    const int kbeg = split * SPLITLEN;
    const int kend = kbeg + SPLITLEN;

    for (int kt = kbeg; kt < kend; kt += 64) {
        #pragma unroll
        for (int j = 0; j < 4; j++) {
            int f   = t + j * 128;
            int r   = f >> 3;
            int dg  = (f & 7) << 3;
            *reinterpret_cast<uint4*>(&Ks[r * HSTR + dg]) =
                *reinterpret_cast<const uint4*>(&khb[(size_t)(kt + r) * DK + dg]);
            *reinterpret_cast<uint4*>(&Vts[r * HSTR + dg]) =
                *reinterpret_cast<const uint4*>(&vtb[(size_t)r * SS + kt + dg]);
        }
        __syncthreads();

        float sacc[8][4];
        #pragma unroll
        for (int nt = 0; nt < 8; nt++) {
            sacc[nt][0] = 0.f; sacc[nt][1] = 0.f;
            sacc[nt][2] = 0.f; sacc[nt][3] = 0.f;
        }
        #pragma unroll
        for (int nt = 0; nt < 8; nt++) {
            const __half* bp = Ks + (8 * nt + lrow) * HSTR + ldk;
            uint32_t bfr[8];
            ldsm4(bfr    , bp     );
            ldsm4(bfr + 4, bp + 32);
            mma_f16(sacc[nt], aq[0], bfr[0], bfr[1]);
            mma_f16(sacc[nt], aq[1], bfr[2], bfr[3]);
            mma_f16(sacc[nt], aq[2], bfr[4], bfr[5]);
            mma_f16(sacc[nt], aq[3], bfr[6], bfr[7]);
        }

        const int mbase = (kt >> 1) + gc;
        #pragma unroll
        for (int nt = 0; nt < 8; nt++) {
            int2 ma = mrow_a[mbase + 4 * nt];
            int2 mb = mrow_b[mbase + 4 * nt];
            sacc[nt][0] = ma.x ? sacc[nt][0] * scale : -1e9f;
            sacc[nt][1] = ma.y ? sacc[nt][1] * scale : -1e9f;
            sacc[nt][2] = mb.x ? sacc[nt][2] * scale : -1e9f;
            sacc[nt][3] = mb.y ? sacc[nt][3] * scale : -1e9f;
        }

        float mxa = -1e30f, mxb = -1e30f;
        #pragma unroll
        for (int nt = 0; nt < 8; nt++) {
            mxa = fmaxf(mxa, fmaxf(sacc[nt][0], sacc[nt][1]));
            mxb = fmaxf(mxb, fmaxf(sacc[nt][2], sacc[nt][3]));
        }
        mxa = fmaxf(mxa, __shfl_xor_sync(0xffffffffu, mxa, 1));
        mxa = fmaxf(mxa, __shfl_xor_sync(0xffffffffu, mxa, 2));
        mxb = fmaxf(mxb, __shfl_xor_sync(0xffffffffu, mxb, 1));
        mxb = fmaxf(mxb, __shfl_xor_sync(0xffffffffu, mxb, 2));

        float mna = fmaxf(m_a, mxa);
        float mnb = fmaxf(m_b, mxb);
        float ca = __expf(m_a - mna);  m_a = mna;
        float cb = __expf(m_b - mnb);  m_b = mnb;

        uint32_t pa[4][4];
        float sla = 0.0f, slb = 0.0f;
        #pragma unroll
        for (int nt = 0; nt < 8; nt++) {
            float p0 = __expf(sacc[nt][0] - m_a);
            float p1 = __expf(sacc[nt][1] - m_a);
            float p2 = __expf(sacc[nt][2] - m_b);
            float p3 = __expf(sacc[nt][3] - m_b);
            sla += p0 + p1;
            slb += p2 + p3;
            int g = nt >> 1;
            int h = (nt & 1) << 1;
            pa[g][h    ] = pack_h2(p0, p1);
            pa[g][h + 1] = pack_h2(p2, p3);
        }
        sla += __shfl_xor_sync(0xffffffffu, sla, 1);
        sla += __shfl_xor_sync(0xffffffffu, sla, 2);
        slb += __shfl_xor_sync(0xffffffffu, slb, 1);
        slb += __shfl_xor_sync(0xffffffffu, slb, 2);
        l_a = l_a * ca + sla;
        l_b = l_b * cb + slb;

        #pragma unroll
        for (int nt = 0; nt < 8; nt++) {
            oacc[nt][0] *= ca; oacc[nt][1] *= ca;
            oacc[nt][2] *= cb; oacc[nt][3] *= cb;
        }

        #pragma unroll
        for (int nt = 0; nt < 8; nt++) {
            const __half* vp = Vts + (8 * nt + lrow) * HSTR + ldk;
            uint32_t bfr[8];
            ldsm4(bfr    , vp     );
            ldsm4(bfr + 4, vp + 32);
            mma_f16(oacc[nt], pa[0], bfr[0], bfr[1]);
            mma_f16(oacc[nt], pa[1], bfr[2], bfr[3]);
            mma_f16(oacc[nt], pa[2], bfr[4], bfr[5]);
            mma_f16(oacc[nt], pa[3], bfr[6], bfr[7]);
        }
        __syncthreads();
    }

    const size_t rowa = (size_t)b * SS + qa;
    const size_t rowb = (size_t)b * SS + qb;
    float* op = g_op[split];
    #pragma unroll
    for (int nt = 0; nt < 8; nt++) {
        float2 oa = { oacc[nt][0], oacc[nt][1] };
        *(float2*)&op[rowa * DK + 8 * nt + 2 * gc] = oa;
        float2 ob = { oacc[nt][2], oacc[nt][3] };
        *(float2*)&op[rowb * DK + 8 * nt + 2 * gc] = ob;
    }
    if (gc == 0) {
        g_m[split * NR + rowa] = m_a;
        g_l[split * NR + rowa] = l_a;
        g_m[split * NR + rowb] = m_b;
        g_l[split * NR + rowb] = l_b;
    }
}

// ---------------------------------------------------------------------------
// Combine the NSPLIT partials; writes fp16 g_atth.
// ---------------------------------------------------------------------------
__global__ __launch_bounds__(128) void attn_combine_kernel()
{
    int idx = blockIdx.x * 128 + threadIdx.x;
    int row = idx >> 4;
    int c4  = (idx & 15) << 2;

    float m[NSPLIT], wgt[NSPLIT];
    float ms = -1e30f;
    #pragma unroll
    for (int s = 0; s < NSPLIT; s++) {
        m[s] = g_m[s * NR + row];
        ms = fmaxf(ms, m[s]);
    }
    float lsum = 0.0f;
    #pragma unroll
    for (int s = 0; s < NSPLIT; s++) {
        wgt[s] = __expf(m[s] - ms);
        lsum += wgt[s] * g_l[s * NR + row];
    }
    float inv = 1.0f / lsum;

    size_t off = (size_t)row * DK + c4;
    float4 o = { 0.f, 0.f, 0.f, 0.f };
    #pragma unroll
    for (int s = 0; s < NSPLIT; s++) {
        float4 p = *(const float4*)&g_op[s][off];
        o.x += wgt[s] * p.x;  o.y += wgt[s] * p.y;
        o.z += wgt[s] * p.z;  o.w += wgt[s] * p.w;
    }
    uint2 h = { pack_h2(o.x * inv, o.y * inv), pack_h2(o.z * inv, o.w * inv) };
    *(uint2*)&g_atth[off] = h;
}

// ---------------------------------------------------------------------------
extern "C" void kernel_launch(void* const* d_in, const int* in_sizes, int n_in,
                              void* d_out, int out_size)
{
    const float* q    = (const float*)d_in[0];
    const float* k    = (const float*)d_in[1];
    const float* v    = (const float*)d_in[2];
    const int*   mask = (const int*)  d_in[3];
    const float* Wq   = (const float*)d_in[4];
    const float* bq   = (const float*)d_in[5];
    const float* Wk   = (const float*)d_in[6];
    const float* bk   = (const float*)d_in[7];
    const float* Wv   = (const float*)d_in[8];
    const float* bv   = (const float*)d_in[9];
    const float* Wo   = (const float*)d_in[10];
    const float* bo   = (const float*)d_in[11];
    float* out = (float*)d_out;

    cudaFuncSetAttribute(qkv_mma_kernel,
                         cudaFuncAttributeMaxDynamicSharedMemorySize, QKV_SMEM);

    const int M = BB * SS;  // 16384

    prep_weights_kernel<<<dim3(DK * DM / (128 * 4), 4), 128>>>(Wq, Wk, Wv, Wo);

    qkv_mma_kernel<<<dim3(M / 64, 3), 128, QKV_SMEM>>>(q, k, v, bq, bk, bv);

    attn_mma_kernel<<<dim3(SS / 64, BB, NSPLIT), 128>>>(mask);
    attn_combine_kernel<<<(NR * 16) / 128, 128>>>();

    outproj_mma_kernel<<<dim3(M / 64, DM / 256), 128>>>(bo, out);
}